// round 8
// baseline (speedup 1.0000x reference)
#include <cuda_runtime.h>
#include <cuda_bf16.h>
#include <math.h>
#include <stdint.h>

#define TT 2048
#define DD 2048
#define NH 16
#define DHV 128
#define DRH 64
#define DCC 512
#define HDIM 192

typedef __nv_bfloat16 bf16;

// ---------------------------------------------------------------------------
// Scratch layout (bytes). bf16 tensors come as hi/lo pairs.
// ---------------------------------------------------------------------------
#define S_H     (2048ULL*2048*2)
#define S_WDKV  (512ULL*2048*2)
#define S_WDQ   (512ULL*2048*2)
#define S_WKR   (64ULL*2048*2)
#define S_WUK   (128ULL*16*512*2)
#define S_WUV   (128ULL*16*512*2)
#define S_WUQ   (128ULL*16*512*2)
#define S_WQR   (64ULL*16*512*2)
#define S_WO    (2048ULL*2048*2)
#define S_CKV   (2048ULL*512*2)
#define S_CQ    (2048ULL*512*2)
#define S_Q     (16ULL*2048*192*2)
#define S_K     (16ULL*2048*192*2)
#define S_V     (16ULL*2048*128*2)
#define S_OUTA  (2048ULL*2048*2)
#define S_KRP   (2048ULL*64*4)
#define S_QRP   (16ULL*2048*64*4)
#define S_LG    (16ULL*2048*2048*4)

#define O_HHI   0ULL
#define O_HLO   (O_HHI+S_H)
#define O_WDKVH (O_HLO+S_H)
#define O_WDKVL (O_WDKVH+S_WDKV)
#define O_WDQH  (O_WDKVL+S_WDKV)
#define O_WDQL  (O_WDQH+S_WDQ)
#define O_WKRH  (O_WDQL+S_WDQ)
#define O_WKRL  (O_WKRH+S_WKR)
#define O_WUKH  (O_WKRL+S_WKR)
#define O_WUKL  (O_WUKH+S_WUK)
#define O_WUVH  (O_WUKL+S_WUK)
#define O_WUVL  (O_WUVH+S_WUV)
#define O_WUQH  (O_WUVL+S_WUV)
#define O_WUQL  (O_WUQH+S_WUQ)
#define O_WQRH  (O_WUQL+S_WUQ)
#define O_WQRL  (O_WQRH+S_WQR)
#define O_WOH   (O_WQRL+S_WQR)
#define O_WOL   (O_WOH+S_WO)
#define O_CKVH  (O_WOL+S_WO)
#define O_CKVL  (O_CKVH+S_CKV)
#define O_CQH   (O_CKVL+S_CKV)
#define O_CQL   (O_CQH+S_CQ)
#define O_QHI   (O_CQL+S_CQ)
#define O_QLO   (O_QHI+S_Q)
#define O_KHI   (O_QLO+S_Q)
#define O_KLO   (O_KHI+S_K)
#define O_VHI   (O_KLO+S_K)
#define O_VLO   (O_VHI+S_V)
#define O_OUTAH (O_VLO+S_V)
#define O_OUTAL (O_OUTAH+S_OUTA)
#define O_KRP   (O_OUTAL+S_OUTA)
#define O_QRP   (O_KRP+S_KRP)
#define O_LG    (O_QRP+S_QRP)
#define SCRATCH_BYTES (O_LG+S_LG)

__device__ __align__(256) unsigned char g_scratch[SCRATCH_BYTES];

// ---------------------------------------------------------------------------
__device__ __forceinline__ uint32_t smem_u32(const void* p) {
    uint32_t a;
    asm("{ .reg .u64 t; cvta.to.shared.u64 t, %1; cvt.u32.u64 %0, t; }"
        : "=r"(a) : "l"(p));
    return a;
}
__device__ __forceinline__ void ldmx4(uint32_t* r, uint32_t addr) {
    asm volatile("ldmatrix.sync.aligned.m8n8.x4.shared.b16 {%0,%1,%2,%3}, [%4];"
                 : "=r"(r[0]), "=r"(r[1]), "=r"(r[2]), "=r"(r[3]) : "r"(addr));
}
__device__ __forceinline__ void ldmx4t(uint32_t* r, uint32_t addr) {
    asm volatile("ldmatrix.sync.aligned.m8n8.x4.trans.shared.b16 {%0,%1,%2,%3}, [%4];"
                 : "=r"(r[0]), "=r"(r[1]), "=r"(r[2]), "=r"(r[3]) : "r"(addr));
}
__device__ __forceinline__ void mma16816(float* c, const uint32_t* a,
                                         uint32_t b0, uint32_t b1) {
    asm volatile(
        "mma.sync.aligned.m16n8k16.row.col.f32.bf16.bf16.f32 "
        "{%0,%1,%2,%3}, {%4,%5,%6,%7}, {%8,%9}, {%0,%1,%2,%3};"
        : "+f"(c[0]), "+f"(c[1]), "+f"(c[2]), "+f"(c[3])
        : "r"(a[0]), "r"(a[1]), "r"(a[2]), "r"(a[3]), "r"(b0), "r"(b1));
}
__device__ __forceinline__ uint32_t bf2_u32(__nv_bfloat162 v) {
    return *reinterpret_cast<uint32_t*>(&v);
}
#define CP16(d, s) asm volatile("cp.async.cg.shared.global [%0], [%1], 16;" \
                                :: "r"(d), "l"(s))
#define CP_COMMIT() asm volatile("cp.async.commit_group;" ::: "memory")
#define CP_WAIT1()  asm volatile("cp.async.wait_group 1;" ::: "memory")
#define CP_WAIT0()  asm volatile("cp.async.wait_group 0;" ::: "memory")

__device__ __forceinline__ void wr_hl(bf16* hi, bf16* lo, size_t o, float v) {
    bf16 h = __float2bfloat16_rn(v);
    hi[o] = h;
    lo[o] = __float2bfloat16_rn(v - __bfloat162float(h));
}

// ---------------------------------------------------------------------------
// fp32 -> bf16 hi/lo split (vectorized)
// ---------------------------------------------------------------------------
__global__ void split_kernel(const float* __restrict__ src, bf16* __restrict__ hi,
                             bf16* __restrict__ lo, int n)
{
    int i = (blockIdx.x * blockDim.x + threadIdx.x) * 4;
    if (i >= n) return;
    float4 v = *(const float4*)(src + i);
    __nv_bfloat162 h0 = __floats2bfloat162_rn(v.x, v.y);
    __nv_bfloat162 h1 = __floats2bfloat162_rn(v.z, v.w);
    float2 f0 = __bfloat1622float2(h0);
    float2 f1 = __bfloat1622float2(h1);
    __nv_bfloat162 l0 = __floats2bfloat162_rn(v.x - f0.x, v.y - f0.y);
    __nv_bfloat162 l1 = __floats2bfloat162_rn(v.z - f1.x, v.w - f1.y);
    *(uint2*)(hi + i) = make_uint2(bf2_u32(h0), bf2_u32(h1));
    *(uint2*)(lo + i) = make_uint2(bf2_u32(l0), bf2_u32(l1));
}

// ---------------------------------------------------------------------------
// HMMA GEMM, pre-split bf16 hi/lo operands, cp.async double-buffered.
// C[m,n] = alpha * sum_k A[m,k]*B[n,k].
// TRANS: A and B stored k-major in gmem (A[k][m], B[k][n]); ldmatrix.trans.
// TRI: lower-triangular tile grid. CK: k starts at m0.
// EPI: 0 = fp32 out (alpha), 1 = bf16 hi/lo out.
// ---------------------------------------------------------------------------
template<int NTILE, bool TRANS, bool TRI, bool CK, int EPI>
__global__ __launch_bounds__(256, 1)
void hgemm(const bf16* __restrict__ Ahi, const bf16* __restrict__ Alo,
           int lda, long long strA,
           const bf16* __restrict__ Bhi, const bf16* __restrict__ Blo,
           int ldb, long long strB,
           float* __restrict__ Cf, bf16* __restrict__ Chi, bf16* __restrict__ Clo,
           long long crs, long long ccs, long long strC,
           int K, float alpha)
{
    constexpr int WN  = NTILE / 2;
    constexpr int NT8 = WN / 8;
    constexpr int NG  = WN / 16;
    constexpr int AB  = TRANS ? 32 * 272 : 128 * 80;
    constexpr int BB  = TRANS ? 32 * 272 : NTILE * 80;
    constexpr int oAL = AB, oBH = 2 * AB;
    constexpr int STAGE = 2 * AB + 2 * BB;

    extern __shared__ char smarr[];
    const uint32_t smb = smem_u32(smarr);
    const int tid = threadIdx.x, wid = tid >> 5, lane = tid & 31;
    const int z = blockIdx.z;
    Ahi += (size_t)z * (size_t)strA;  Alo += (size_t)z * (size_t)strA;
    Bhi += (size_t)z * (size_t)strB;  Blo += (size_t)z * (size_t)strB;
    if (EPI == 0) { Cf += (size_t)z * (size_t)strC; }
    else { Chi += (size_t)z * (size_t)strC; Clo += (size_t)z * (size_t)strC; }

    int m0, n0;
    if (TRI) {
        int x = blockIdx.x;
        int tm = (int)((sqrtf(8.0f * x + 1.0f) - 1.0f) * 0.5f);
        while ((tm + 1) * (tm + 2) / 2 <= x) tm++;
        while (tm * (tm + 1) / 2 > x) tm--;
        int tn = x - tm * (tm + 1) / 2;
        m0 = tm * 128; n0 = tn * 128;
    } else {
        m0 = blockIdx.y * 128;
        n0 = blockIdx.x * NTILE;
    }

    const int kbeg  = CK ? m0 : 0;
    const int niter = (K - kbeg) / 32;

    auto issue = [&](int it) {
        const int kk0 = kbeg + it * 32;
        const uint32_t sb = smb + (it & 1) * STAGE;
        if (!TRANS) {
#pragma unroll
            for (int c = tid; c < 512; c += 256) {
                int row = c >> 2, kc = (c & 3) * 8;
                uint32_t d = sb + row * 80 + kc * 2;
                const bf16* s = Ahi + (size_t)(m0 + row) * lda + kk0 + kc;
                CP16(d, s);
                CP16(d + oAL, Alo + (s - Ahi));
            }
#pragma unroll
            for (int c = tid; c < NTILE * 4; c += 256) {
                int row = c >> 2, kc = (c & 3) * 8;
                uint32_t d = sb + oBH + row * 80 + kc * 2;
                const bf16* s = Bhi + (size_t)(n0 + row) * ldb + kk0 + kc;
                CP16(d, s);
                CP16(d + BB, Blo + (s - Bhi));
            }
        } else {
#pragma unroll
            for (int c = tid; c < 512; c += 256) {
                int kr = c >> 4, mc = (c & 15) * 8;
                uint32_t d = sb + kr * 272 + mc * 2;
                const bf16* s = Ahi + (size_t)(kk0 + kr) * lda + m0 + mc;
                CP16(d, s);
                CP16(d + oAL, Alo + (s - Ahi));
            }
#pragma unroll
            for (int c = tid; c < 512; c += 256) {
                int kr = c >> 4, nc = (c & 15) * 8;
                uint32_t d = sb + oBH + kr * 272 + nc * 2;
                const bf16* s = Bhi + (size_t)(kk0 + kr) * ldb + n0 + nc;
                CP16(d, s);
                CP16(d + BB, Blo + (s - Bhi));
            }
        }
    };

    float acc[2][NT8][4];
#pragma unroll
    for (int a = 0; a < 2; a++)
#pragma unroll
        for (int b = 0; b < NT8; b++)
#pragma unroll
            for (int c = 0; c < 4; c++) acc[a][b][c] = 0.0f;

    const int wm  = (wid & 3) * 32;
    const int wnb = (wid >> 2) * WN;

    issue(0);
    CP_COMMIT();

    for (int it = 0; it < niter; it++) {
        if (it + 1 < niter) { issue(it + 1); CP_COMMIT(); CP_WAIT1(); }
        else                { CP_WAIT0(); }
        __syncthreads();

        const uint32_t sb = smb + (it & 1) * STAGE;
#pragma unroll
        for (int kk = 0; kk < 32; kk += 16) {
            uint32_t ah[2][4], al[2][4];
#pragma unroll
            for (int mt = 0; mt < 2; mt++) {
                if (!TRANS) {
                    int r = wm + mt * 16 + (lane & 15);
                    uint32_t a = sb + r * 80 + kk * 2 + ((lane >> 4) << 4);
                    ldmx4(ah[mt], a);
                    ldmx4(al[mt], a + oAL);
                } else {
                    int kr = kk + ((lane >> 4) << 3) + (lane & 7);
                    int mc = wm + mt * 16 + ((lane >> 3) & 1) * 8;
                    uint32_t a = sb + kr * 272 + mc * 2;
                    ldmx4t(ah[mt], a);
                    ldmx4t(al[mt], a + oAL);
                }
            }
#pragma unroll
            for (int ng = 0; ng < NG; ng++) {
                uint32_t bh[4], bl[4];
                if (!TRANS) {
                    int r = wnb + ng * 16 + (lane & 15);
                    uint32_t a = sb + oBH + r * 80 + kk * 2 + ((lane >> 4) << 4);
                    ldmx4(bh, a);
                    ldmx4(bl, a + BB);
                } else {
                    int kr = kk + ((lane >> 4) << 3) + (lane & 7);
                    int nc = wnb + ng * 16 + ((lane >> 3) & 1) * 8;
                    uint32_t a = sb + oBH + kr * 272 + nc * 2;
                    ldmx4t(bh, a);
                    ldmx4t(bl, a + BB);
                }
#pragma unroll
                for (int hf = 0; hf < 2; hf++) {
#pragma unroll
                    for (int mt = 0; mt < 2; mt++) {
                        float* c = acc[mt][ng * 2 + hf];
                        mma16816(c, ah[mt], bh[hf], bh[hf + 2]);
                        mma16816(c, ah[mt], bl[hf], bl[hf + 2]);
                        mma16816(c, al[mt], bh[hf], bh[hf + 2]);
                    }
                }
            }
        }
        __syncthreads();
    }

    // Epilogue
#pragma unroll
    for (int mt = 0; mt < 2; mt++) {
#pragma unroll
        for (int nt = 0; nt < NT8; nt++) {
            int gm = m0 + wm + mt * 16 + (lane >> 2);
            int gn = n0 + wnb + nt * 8 + (lane & 3) * 2;
            float v0 = acc[mt][nt][0] * alpha;
            float v1 = acc[mt][nt][1] * alpha;
            float v2 = acc[mt][nt][2] * alpha;
            float v3 = acc[mt][nt][3] * alpha;
            if (EPI == 0) {
                if (ccs == 1) {
                    *(float2*)&Cf[(size_t)gm * crs + gn]       = make_float2(v0, v1);
                    *(float2*)&Cf[(size_t)(gm + 8) * crs + gn] = make_float2(v2, v3);
                } else {
                    Cf[(size_t)gm * crs + (size_t)gn * ccs]             = v0;
                    Cf[(size_t)gm * crs + (size_t)(gn + 1) * ccs]       = v1;
                    Cf[(size_t)(gm + 8) * crs + (size_t)gn * ccs]       = v2;
                    Cf[(size_t)(gm + 8) * crs + (size_t)(gn + 1) * ccs] = v3;
                }
            } else {
                wr_hl(Chi, Clo, (size_t)gm * crs + (size_t)gn * ccs, v0);
                wr_hl(Chi, Clo, (size_t)gm * crs + (size_t)(gn + 1) * ccs, v1);
                wr_hl(Chi, Clo, (size_t)(gm + 8) * crs + (size_t)gn * ccs, v2);
                wr_hl(Chi, Clo, (size_t)(gm + 8) * crs + (size_t)(gn + 1) * ccs, v3);
            }
        }
    }
}

// ---------------------------------------------------------------------------
// RoPE: q_r (fp32 temp) -> q hi/lo cols 128..191
// ---------------------------------------------------------------------------
__global__ void rope_q_split(const float* __restrict__ qrp, bf16* __restrict__ qhi,
                             bf16* __restrict__ qlo, const float* __restrict__ freqs)
{
    int idx = blockIdx.x * blockDim.x + threadIdx.x;
    if (idx >= NH * TT * 32) return;
    int i = idx & 31;
    int t = (idx >> 5) & (TT - 1);
    int n = idx >> 16;
    const float* src = qrp + ((size_t)n * TT + t) * DRH;
    float fr = freqs[t * 32 + i];
    float c = cosf(fr), s = sinf(fr);
    float re = src[i], im = src[i + 32];
    size_t base = ((size_t)n * TT + t) * HDIM + DHV;
    wr_hl(qhi, qlo, base + i,      re * c - im * s);
    wr_hl(qhi, qlo, base + i + 32, re * s + im * c);
}

__global__ void rope_k_split(const float* __restrict__ krp, bf16* __restrict__ khi,
                             bf16* __restrict__ klo, const float* __restrict__ freqs)
{
    int idx = blockIdx.x * blockDim.x + threadIdx.x;
    if (idx >= TT * 32) return;
    int i = idx & 31;
    int t = idx >> 5;
    float fr = freqs[t * 32 + i];
    float c = cosf(fr), s = sinf(fr);
    float re = krp[t * 64 + i];
    float im = krp[t * 64 + i + 32];
    float o1 = (re * c - im * s) * (1.0f / 16.0f);
    float o2 = (re * s + im * c) * (1.0f / 16.0f);
#pragma unroll
    for (int n = 0; n < NH; n++) {
        size_t base = ((size_t)n * TT + t) * HDIM + DHV;
        wr_hl(khi, klo, base + i, o1);
        wr_hl(khi, klo, base + i + 32, o2);
    }
}

// ---------------------------------------------------------------------------
// Causal softmax; writes S as bf16 hi/lo IN PLACE over the fp32 row:
// row's 8KB = [2048 hi bf16][2048 lo bf16].
// ---------------------------------------------------------------------------
__global__ __launch_bounds__(256)
void softmax_causal_split(float* __restrict__ L)
{
    int row = blockIdx.x;               // n*2048 + t
    int t = row & (TT - 1);
    int nvalid = t + 1;
    float* p = L + (size_t)row * TT;
    int tid = threadIdx.x;
    __shared__ float red[256];

    float v[8];
    float m = -3.4e38f;
#pragma unroll
    for (int k = 0; k < 8; k++) {
        int idx = tid + k * 256;
        v[k] = (idx < nvalid) ? p[idx] : -3.4e38f;
        m = fmaxf(m, v[k]);
    }
    red[tid] = m;
    __syncthreads();
    for (int s = 128; s > 0; s >>= 1) {
        if (tid < s) red[tid] = fmaxf(red[tid], red[tid + s]);
        __syncthreads();
    }
    m = red[0];
    __syncthreads();

    float sum = 0.0f;
#pragma unroll
    for (int k = 0; k < 8; k++) {
        v[k] = expf(v[k] - m);
        sum += v[k];
    }
    red[tid] = sum;
    __syncthreads();
    for (int s = 128; s > 0; s >>= 1) {
        if (tid < s) red[tid] += red[tid + s];
        __syncthreads();
    }
    float inv = 1.0f / red[0];
    __syncthreads();   // all reads of this row complete before aliased writes

    bf16* ph = (bf16*)p;
#pragma unroll
    for (int k = 0; k < 8; k++) {
        int idx = tid + k * 256;
        float val = (idx < nvalid) ? v[k] * inv : 0.0f;
        bf16 h = __float2bfloat16_rn(val);
        ph[idx]        = h;
        ph[2048 + idx] = __float2bfloat16_rn(val - __bfloat162float(h));
    }
}

// ---------------------------------------------------------------------------
extern "C" void kernel_launch(void* const* d_in, const int* in_sizes, int n_in,
                              void* d_out, int out_size)
{
    const float* h      = (const float*)d_in[0];
    const float* freqs  = (const float*)d_in[1];
    const float* w_dkv  = (const float*)d_in[3];
    const float* w_uk   = (const float*)d_in[4];
    const float* w_uv   = (const float*)d_in[5];
    const float* w_dq   = (const float*)d_in[6];
    const float* w_uq   = (const float*)d_in[7];
    const float* w_qr   = (const float*)d_in[8];
    const float* w_kr   = (const float*)d_in[9];
    const float* w_o    = (const float*)d_in[10];
    float* out = (float*)d_out;

    unsigned char* sc = nullptr;
    cudaGetSymbolAddress((void**)&sc, g_scratch);
    bf16* hhi   = (bf16*)(sc + O_HHI);   bf16* hlo   = (bf16*)(sc + O_HLO);
    bf16* wdkvh = (bf16*)(sc + O_WDKVH); bf16* wdkvl = (bf16*)(sc + O_WDKVL);
    bf16* wdqh  = (bf16*)(sc + O_WDQH);  bf16* wdql  = (bf16*)(sc + O_WDQL);
    bf16* wkrh  = (bf16*)(sc + O_WKRH);  bf16* wkrl  = (bf16*)(sc + O_WKRL);
    bf16* wukh  = (bf16*)(sc + O_WUKH);  bf16* wukl  = (bf16*)(sc + O_WUKL);
    bf16* wuvh  = (bf16*)(sc + O_WUVH);  bf16* wuvl  = (bf16*)(sc + O_WUVL);
    bf16* wuqh  = (bf16*)(sc + O_WUQH);  bf16* wuql  = (bf16*)(sc + O_WUQL);
    bf16* wqrh  = (bf16*)(sc + O_WQRH);  bf16* wqrl  = (bf16*)(sc + O_WQRL);
    bf16* woh   = (bf16*)(sc + O_WOH);   bf16* wol   = (bf16*)(sc + O_WOL);
    bf16* ckvh  = (bf16*)(sc + O_CKVH);  bf16* ckvl  = (bf16*)(sc + O_CKVL);
    bf16* cqh   = (bf16*)(sc + O_CQH);   bf16* cql   = (bf16*)(sc + O_CQL);
    bf16* qhi   = (bf16*)(sc + O_QHI);   bf16* qlo   = (bf16*)(sc + O_QLO);
    bf16* khi   = (bf16*)(sc + O_KHI);   bf16* klo   = (bf16*)(sc + O_KLO);
    bf16* vhi   = (bf16*)(sc + O_VHI);   bf16* vlo   = (bf16*)(sc + O_VLO);
    bf16* outah = (bf16*)(sc + O_OUTAH); bf16* outal = (bf16*)(sc + O_OUTAL);
    float* krp  = (float*)(sc + O_KRP);
    float* qrp  = (float*)(sc + O_QRP);
    float* lg   = (float*)(sc + O_LG);
    bf16* Shi   = (bf16*)(sc + O_LG);           // aliased: row = [2048 hi][2048 lo]
    bf16* Slo   = Shi + 2048;

    // dynamic smem sizes: 2 stages * (2*AB + 2*BB)
    const int SM64  = 2 * (2 * 128 * 80 + 2 * 64 * 80);    // 61440
    const int SM128 = 2 * (2 * 128 * 80 + 2 * 128 * 80);   // 81920
    const int SMT   = 2 * (4 * 32 * 272);                  // 69632
    cudaFuncSetAttribute(hgemm<64, false, false, false, 1>,
                         cudaFuncAttributeMaxDynamicSharedMemorySize, SM64);
    cudaFuncSetAttribute(hgemm<64, false, false, false, 0>,
                         cudaFuncAttributeMaxDynamicSharedMemorySize, SM64);
    cudaFuncSetAttribute(hgemm<128, false, false, false, 1>,
                         cudaFuncAttributeMaxDynamicSharedMemorySize, SM128);
    cudaFuncSetAttribute(hgemm<128, false, true, false, 0>,
                         cudaFuncAttributeMaxDynamicSharedMemorySize, SM128);
    cudaFuncSetAttribute(hgemm<128, true, false, true, 1>,
                         cudaFuncAttributeMaxDynamicSharedMemorySize, SMT);
    cudaFuncSetAttribute(hgemm<128, false, false, false, 0>,
                         cudaFuncAttributeMaxDynamicSharedMemorySize, SM128);

    const float scale = 1.0f / sqrtf((float)HDIM);
    dim3 blk(256);

    // 0) split inputs + weights to bf16 hi/lo
    split_kernel<<<4096, 256>>>(h, hhi, hlo, 2048 * 2048);
    split_kernel<<<1024, 256>>>(w_dkv, wdkvh, wdkvl, 512 * 2048);
    split_kernel<<<1024, 256>>>(w_dq, wdqh, wdql, 512 * 2048);
    split_kernel<<<128, 256>>>(w_kr, wkrh, wkrl, 64 * 2048);
    split_kernel<<<1024, 256>>>(w_uk, wukh, wukl, 128 * 16 * 512);
    split_kernel<<<1024, 256>>>(w_uv, wuvh, wuvl, 128 * 16 * 512);
    split_kernel<<<1024, 256>>>(w_uq, wuqh, wuql, 128 * 16 * 512);
    split_kernel<<<512, 256>>>(w_qr, wqrh, wqrl, 64 * 16 * 512);
    split_kernel<<<4096, 256>>>(w_o, woh, wol, 2048 * 2048);

    // 1) down projections
    hgemm<64, false, false, false, 1><<<dim3(8, 16, 1), blk, SM64>>>(
        hhi, hlo, DD, 0, wdkvh, wdkvl, DD, 0,
        nullptr, ckvh, ckvl, DCC, 1, 0, DD, 1.0f);
    hgemm<64, false, false, false, 1><<<dim3(8, 16, 1), blk, SM64>>>(
        hhi, hlo, DD, 0, wdqh, wdql, DD, 0,
        nullptr, cqh, cql, DCC, 1, 0, DD, 1.0f);
    hgemm<64, false, false, false, 0><<<dim3(1, 16, 1), blk, SM64>>>(
        hhi, hlo, DD, 0, wkrh, wkrl, DD, 0,
        krp, nullptr, nullptr, DRH, 1, 0, DD, 1.0f);

    // 2) per-head up-projections (z = head)
    hgemm<128, false, false, false, 1><<<dim3(1, 16, NH), blk, SM128>>>(
        ckvh, ckvl, DCC, 0, wukh, wukl, NH * DCC, DCC,
        nullptr, khi, klo, HDIM, 1, (long long)TT * HDIM, DCC, 1.0f);
    hgemm<128, false, false, false, 1><<<dim3(1, 16, NH), blk, SM128>>>(
        ckvh, ckvl, DCC, 0, wuvh, wuvl, NH * DCC, DCC,
        nullptr, vhi, vlo, DHV, 1, (long long)TT * DHV, DCC, 1.0f);
    hgemm<128, false, false, false, 1><<<dim3(1, 16, NH), blk, SM128>>>(
        cqh, cql, DCC, 0, wuqh, wuql, NH * DCC, DCC,
        nullptr, qhi, qlo, HDIM, 1, (long long)TT * HDIM, DCC, 1.0f);
    hgemm<64, false, false, false, 0><<<dim3(1, 16, NH), blk, SM64>>>(
        cqh, cql, DCC, 0, wqrh, wqrl, NH * DCC, DCC,
        qrp, nullptr, nullptr, DRH, 1, (long long)TT * DRH, DCC, 1.0f);

    // 3) RoPE -> q/k hi/lo cols 128..191
    rope_q_split<<<(NH * TT * 32 + 255) / 256, 256>>>(qrp, qhi, qlo, freqs);
    rope_k_split<<<(TT * 32 + 255) / 256, 256>>>(krp, khi, klo, freqs);

    // 4) logits = q k^T * scale (lower-triangle tiles; 136 per head)
    hgemm<128, false, true, false, 0><<<dim3(136, 1, NH), blk, SM128>>>(
        qhi, qlo, HDIM, (long long)TT * HDIM, khi, klo, HDIM, (long long)TT * HDIM,
        lg, nullptr, nullptr, TT, 1, (long long)TT * TT, HDIM, scale);

    // 5) causal softmax; emits S as bf16 hi/lo in place
    softmax_causal_split<<<NH * TT, 256>>>(lg);

    // 6) out[l,e] = sum_t S[t,l] V[t,e]; trans staging + ldmatrix.trans
    //    S rows: 4096 bf16 stride; V rows: 128 bf16 stride. k skip: t >= m0.
    hgemm<128, true, false, true, 1><<<dim3(1, 16, NH), blk, SMT>>>(
        Shi, Slo, 2 * TT, (long long)TT * 2 * TT, vhi, vlo, DHV, (long long)TT * DHV,
        nullptr, outah, outal, DD, NH, 1, TT, 1.0f);

    // 7) final = outa . w_o^T (both bf16 hi/lo), fp32 out
    hgemm<128, false, false, false, 0><<<dim3(16, 16, 1), blk, SM128>>>(
        outah, outal, DD, 0, woh, wol, DD, 0,
        out, nullptr, nullptr, DD, 1, 0, DD, 1.0f);
}

// round 12
// speedup vs baseline: 1.6459x; 1.6459x over previous
#include <cuda_runtime.h>
#include <cuda_bf16.h>
#include <math.h>
#include <stdint.h>

#define TT 2048
#define DD 2048
#define NH 16
#define DHV 128
#define DRH 64
#define DCC 512
#define HDIM 192

typedef __nv_bfloat16 bf16;

// ---------------------------------------------------------------------------
// Scratch layout (bytes). bf16 tensors come as hi/lo pairs.
// ---------------------------------------------------------------------------
#define S_H     (2048ULL*2048*2)
#define S_WDKV  (512ULL*2048*2)
#define S_WDQ   (512ULL*2048*2)
#define S_WKR   (64ULL*2048*2)
#define S_WUK   (128ULL*16*512*2)
#define S_WUV   (128ULL*16*512*2)
#define S_WUQ   (128ULL*16*512*2)
#define S_WQR   (64ULL*16*512*2)
#define S_WO    (2048ULL*2048*2)
#define S_CKV   (2048ULL*512*2)
#define S_CQ    (2048ULL*512*2)
#define S_Q     (16ULL*2048*192*2)
#define S_K     (16ULL*2048*192*2)
#define S_V     (16ULL*2048*128*2)
#define S_OUTA  (2048ULL*2048*2)
#define S_KRP   (2048ULL*64*4)
#define S_QRP   (16ULL*2048*64*4)
#define S_LG    (16ULL*2048*2048*4)

#define O_HHI   0ULL
#define O_HLO   (O_HHI+S_H)
#define O_WDKVH (O_HLO+S_H)
#define O_WDKVL (O_WDKVH+S_WDKV)
#define O_WDQH  (O_WDKVL+S_WDKV)
#define O_WDQL  (O_WDQH+S_WDQ)
#define O_WKRH  (O_WDQL+S_WDQ)
#define O_WKRL  (O_WKRH+S_WKR)
#define O_WUKH  (O_WKRL+S_WKR)
#define O_WUKL  (O_WUKH+S_WUK)
#define O_WUVH  (O_WUKL+S_WUK)
#define O_WUVL  (O_WUVH+S_WUV)
#define O_WUQH  (O_WUVL+S_WUV)
#define O_WUQL  (O_WUQH+S_WUQ)
#define O_WQRH  (O_WUQL+S_WUQ)
#define O_WQRL  (O_WQRH+S_WQR)
#define O_WOH   (O_WQRL+S_WQR)
#define O_WOL   (O_WOH+S_WO)
#define O_CKVH  (O_WOL+S_WO)
#define O_CKVL  (O_CKVH+S_CKV)
#define O_CQH   (O_CKVL+S_CKV)
#define O_CQL   (O_CQH+S_CQ)
#define O_QHI   (O_CQL+S_CQ)
#define O_QLO   (O_QHI+S_Q)
#define O_KHI   (O_QLO+S_Q)
#define O_KLO   (O_KHI+S_K)
#define O_VHI   (O_KLO+S_K)
#define O_VLO   (O_VHI+S_V)
#define O_OUTAH (O_VLO+S_V)
#define O_OUTAL (O_OUTAH+S_OUTA)
#define O_KRP   (O_OUTAL+S_OUTA)
#define O_QRP   (O_KRP+S_KRP)
#define O_LG    (O_QRP+S_QRP)
#define SCRATCH_BYTES (O_LG+S_LG)

__device__ __align__(256) unsigned char g_scratch[SCRATCH_BYTES];

// ---------------------------------------------------------------------------
__device__ __forceinline__ uint32_t smem_u32(const void* p) {
    uint32_t a;
    asm("{ .reg .u64 t; cvta.to.shared.u64 t, %1; cvt.u32.u64 %0, t; }"
        : "=r"(a) : "l"(p));
    return a;
}
__device__ __forceinline__ void ldmx4(uint32_t* r, uint32_t addr) {
    asm volatile("ldmatrix.sync.aligned.m8n8.x4.shared.b16 {%0,%1,%2,%3}, [%4];"
                 : "=r"(r[0]), "=r"(r[1]), "=r"(r[2]), "=r"(r[3]) : "r"(addr));
}
__device__ __forceinline__ void ldmx4t(uint32_t* r, uint32_t addr) {
    asm volatile("ldmatrix.sync.aligned.m8n8.x4.trans.shared.b16 {%0,%1,%2,%3}, [%4];"
                 : "=r"(r[0]), "=r"(r[1]), "=r"(r[2]), "=r"(r[3]) : "r"(addr));
}
__device__ __forceinline__ void mma16816(float* c, const uint32_t* a,
                                         uint32_t b0, uint32_t b1) {
    asm volatile(
        "mma.sync.aligned.m16n8k16.row.col.f32.bf16.bf16.f32 "
        "{%0,%1,%2,%3}, {%4,%5,%6,%7}, {%8,%9}, {%0,%1,%2,%3};"
        : "+f"(c[0]), "+f"(c[1]), "+f"(c[2]), "+f"(c[3])
        : "r"(a[0]), "r"(a[1]), "r"(a[2]), "r"(a[3]), "r"(b0), "r"(b1));
}
__device__ __forceinline__ uint32_t bf2_u32(__nv_bfloat162 v) {
    return *reinterpret_cast<uint32_t*>(&v);
}
#define CP16(d, s) asm volatile("cp.async.cg.shared.global [%0], [%1], 16;" \
                                :: "r"(d), "l"(s))
#define CP_COMMIT() asm volatile("cp.async.commit_group;" ::: "memory")
#define CP_WAIT1()  asm volatile("cp.async.wait_group 1;" ::: "memory")
#define CP_WAIT0()  asm volatile("cp.async.wait_group 0;" ::: "memory")

__device__ __forceinline__ void wr_hl(bf16* hi, bf16* lo, size_t o, float v) {
    bf16 h = __float2bfloat16_rn(v);
    hi[o] = h;
    lo[o] = __float2bfloat16_rn(v - __bfloat162float(h));
}
// paired (adjacent-column) hi/lo store: one 4B store each for hi and lo
__device__ __forceinline__ void wr_hl2(bf16* hi, bf16* lo, size_t o,
                                       float v0, float v1) {
    __nv_bfloat162 h = __floats2bfloat162_rn(v0, v1);
    float2 f = __bfloat1622float2(h);
    __nv_bfloat162 l = __floats2bfloat162_rn(v0 - f.x, v1 - f.y);
    *(uint32_t*)(hi + o) = bf2_u32(h);
    *(uint32_t*)(lo + o) = bf2_u32(l);
}

// ---------------------------------------------------------------------------
// Fused fp32 -> bf16 hi/lo split for all 9 tensors (one launch).
// ---------------------------------------------------------------------------
struct SplitArgs {
    const float* src[9];
    bf16* hi[9];
    bf16* lo[9];
    int n[9];
};

__global__ void split_all_kernel(SplitArgs a)
{
    int z = blockIdx.y;
    const float* __restrict__ src = a.src[z];
    bf16* __restrict__ hi = a.hi[z];
    bf16* __restrict__ lo = a.lo[z];
    int n = a.n[z];
    int stride = gridDim.x * blockDim.x * 4;
    for (int i = (blockIdx.x * blockDim.x + threadIdx.x) * 4; i < n; i += stride) {
        float4 v = *(const float4*)(src + i);
        __nv_bfloat162 h0 = __floats2bfloat162_rn(v.x, v.y);
        __nv_bfloat162 h1 = __floats2bfloat162_rn(v.z, v.w);
        float2 f0 = __bfloat1622float2(h0);
        float2 f1 = __bfloat1622float2(h1);
        __nv_bfloat162 l0 = __floats2bfloat162_rn(v.x - f0.x, v.y - f0.y);
        __nv_bfloat162 l1 = __floats2bfloat162_rn(v.z - f1.x, v.w - f1.y);
        *(uint2*)(hi + i) = make_uint2(bf2_u32(h0), bf2_u32(h1));
        *(uint2*)(lo + i) = make_uint2(bf2_u32(l0), bf2_u32(l1));
    }
}

// ---------------------------------------------------------------------------
// HMMA GEMM, pre-split bf16 hi/lo operands, 3-stage cp.async pipeline.
// C[m,n] = alpha * sum_k A[m,k]*B[n,k].
// TRANS: A and B stored k-major in gmem (A[k][m], B[k][n]); ldmatrix.trans.
// TRI: lower-triangular tile grid. CK: k starts at m0.
// EPI: 0 = fp32 out (alpha), 1 = bf16 hi/lo out.
// ---------------------------------------------------------------------------
template<int NTILE, bool TRANS, bool TRI, bool CK, int EPI>
__global__ __launch_bounds__(256, 1)
void hgemm(const bf16* __restrict__ Ahi, const bf16* __restrict__ Alo,
           int lda, long long strA,
           const bf16* __restrict__ Bhi, const bf16* __restrict__ Blo,
           int ldb, long long strB,
           float* __restrict__ Cf, bf16* __restrict__ Chi, bf16* __restrict__ Clo,
           long long crs, long long ccs, long long strC,
           int K, float alpha)
{
    constexpr int WN  = NTILE / 2;
    constexpr int NT8 = WN / 8;
    constexpr int NG  = WN / 16;
    constexpr int AB  = TRANS ? 32 * 272 : 128 * 80;
    constexpr int BB  = TRANS ? 32 * 272 : NTILE * 80;
    constexpr int oAL = AB, oBH = 2 * AB;
    constexpr int STAGE = 2 * AB + 2 * BB;

    extern __shared__ char smarr[];
    const uint32_t smb = smem_u32(smarr);
    const int tid = threadIdx.x, wid = tid >> 5, lane = tid & 31;
    const int z = blockIdx.z;
    Ahi += (size_t)z * (size_t)strA;  Alo += (size_t)z * (size_t)strA;
    Bhi += (size_t)z * (size_t)strB;  Blo += (size_t)z * (size_t)strB;
    if (EPI == 0) { Cf += (size_t)z * (size_t)strC; }
    else { Chi += (size_t)z * (size_t)strC; Clo += (size_t)z * (size_t)strC; }

    int m0, n0;
    if (TRI) {
        int x = blockIdx.x;
        int tm = (int)((sqrtf(8.0f * x + 1.0f) - 1.0f) * 0.5f);
        while ((tm + 1) * (tm + 2) / 2 <= x) tm++;
        while (tm * (tm + 1) / 2 > x) tm--;
        int tn = x - tm * (tm + 1) / 2;
        m0 = tm * 128; n0 = tn * 128;
    } else {
        m0 = blockIdx.y * 128;
        n0 = blockIdx.x * NTILE;
    }

    const int kbeg  = CK ? m0 : 0;
    const int niter = (K - kbeg) / 32;

    auto issue = [&](int it) {
        const int kk0 = kbeg + it * 32;
        const uint32_t sb = smb + (it % 3) * STAGE;
        if (!TRANS) {
#pragma unroll
            for (int c = tid; c < 512; c += 256) {
                int row = c >> 2, kc = (c & 3) * 8;
                uint32_t d = sb + row * 80 + kc * 2;
                const bf16* s = Ahi + (size_t)(m0 + row) * lda + kk0 + kc;
                CP16(d, s);
                CP16(d + oAL, Alo + (s - Ahi));
            }
#pragma unroll
            for (int c = tid; c < NTILE * 4; c += 256) {
                int row = c >> 2, kc = (c & 3) * 8;
                uint32_t d = sb + oBH + row * 80 + kc * 2;
                const bf16* s = Bhi + (size_t)(n0 + row) * ldb + kk0 + kc;
                CP16(d, s);
                CP16(d + BB, Blo + (s - Bhi));
            }
        } else {
#pragma unroll
            for (int c = tid; c < 512; c += 256) {
                int kr = c >> 4, mc = (c & 15) * 8;
                uint32_t d = sb + kr * 272 + mc * 2;
                const bf16* s = Ahi + (size_t)(kk0 + kr) * lda + m0 + mc;
                CP16(d, s);
                CP16(d + oAL, Alo + (s - Ahi));
            }
#pragma unroll
            for (int c = tid; c < 512; c += 256) {
                int kr = c >> 4, nc = (c & 15) * 8;
                uint32_t d = sb + oBH + kr * 272 + nc * 2;
                const bf16* s = Bhi + (size_t)(kk0 + kr) * ldb + n0 + nc;
                CP16(d, s);
                CP16(d + BB, Blo + (s - Bhi));
            }
        }
    };

    float acc[2][NT8][4];
#pragma unroll
    for (int a = 0; a < 2; a++)
#pragma unroll
        for (int b = 0; b < NT8; b++)
#pragma unroll
            for (int c = 0; c < 4; c++) acc[a][b][c] = 0.0f;

    const int wm  = (wid & 3) * 32;
    const int wnb = (wid >> 2) * WN;

    // 3-stage pipeline prologue
    issue(0); CP_COMMIT();
    if (niter > 1) { issue(1); CP_COMMIT(); }

    for (int it = 0; it < niter; it++) {
        // wait for group 'it' (at most one younger group stays in flight)
        if (it + 1 < niter) CP_WAIT1(); else CP_WAIT0();
        __syncthreads();
        // prefetch stage it+2 (overwrites stage of it-1; readers done behind
        // the trailing __syncthreads of iter it-1)
        if (it + 2 < niter) { issue(it + 2); CP_COMMIT(); }

        const uint32_t sb = smb + (it % 3) * STAGE;
#pragma unroll
        for (int kk = 0; kk < 32; kk += 16) {
            uint32_t ah[2][4], al[2][4];
#pragma unroll
            for (int mt = 0; mt < 2; mt++) {
                if (!TRANS) {
                    int r = wm + mt * 16 + (lane & 15);
                    uint32_t a = sb + r * 80 + kk * 2 + ((lane >> 4) << 4);
                    ldmx4(ah[mt], a);
                    ldmx4(al[mt], a + oAL);
                } else {
                    int kr = kk + ((lane >> 4) << 3) + (lane & 7);
                    int mc = wm + mt * 16 + ((lane >> 3) & 1) * 8;
                    uint32_t a = sb + kr * 272 + mc * 2;
                    ldmx4t(ah[mt], a);
                    ldmx4t(al[mt], a + oAL);
                }
            }
#pragma unroll
            for (int ng = 0; ng < NG; ng++) {
                uint32_t bh[4], bl[4];
                if (!TRANS) {
                    int r = wnb + ng * 16 + (lane & 15);
                    uint32_t a = sb + oBH + r * 80 + kk * 2 + ((lane >> 4) << 4);
                    ldmx4(bh, a);
                    ldmx4(bl, a + BB);
                } else {
                    int kr = kk + ((lane >> 4) << 3) + (lane & 7);
                    int nc = wnb + ng * 16 + ((lane >> 3) & 1) * 8;
                    uint32_t a = sb + oBH + kr * 272 + nc * 2;
                    ldmx4t(bh, a);
                    ldmx4t(bl, a + BB);
                }
#pragma unroll
                for (int hf = 0; hf < 2; hf++) {
#pragma unroll
                    for (int mt = 0; mt < 2; mt++) {
                        float* c = acc[mt][ng * 2 + hf];
                        mma16816(c, ah[mt], bh[hf], bh[hf + 2]);
                        mma16816(c, ah[mt], bl[hf], bl[hf + 2]);
                        mma16816(c, al[mt], bh[hf], bh[hf + 2]);
                    }
                }
            }
        }
        __syncthreads();   // all warps done reading stage it before it+3 issue
    }

    // Epilogue
#pragma unroll
    for (int mt = 0; mt < 2; mt++) {
#pragma unroll
        for (int nt = 0; nt < NT8; nt++) {
            int gm = m0 + wm + mt * 16 + (lane >> 2);
            int gn = n0 + wnb + nt * 8 + (lane & 3) * 2;
            float v0 = acc[mt][nt][0] * alpha;
            float v1 = acc[mt][nt][1] * alpha;
            float v2 = acc[mt][nt][2] * alpha;
            float v3 = acc[mt][nt][3] * alpha;
            if (EPI == 0) {
                if (ccs == 1) {
                    *(float2*)&Cf[(size_t)gm * crs + gn]       = make_float2(v0, v1);
                    *(float2*)&Cf[(size_t)(gm + 8) * crs + gn] = make_float2(v2, v3);
                } else {
                    Cf[(size_t)gm * crs + (size_t)gn * ccs]             = v0;
                    Cf[(size_t)gm * crs + (size_t)(gn + 1) * ccs]       = v1;
                    Cf[(size_t)(gm + 8) * crs + (size_t)gn * ccs]       = v2;
                    Cf[(size_t)(gm + 8) * crs + (size_t)(gn + 1) * ccs] = v3;
                }
            } else {
                if (ccs == 1) {
                    wr_hl2(Chi, Clo, (size_t)gm * crs + gn, v0, v1);
                    wr_hl2(Chi, Clo, (size_t)(gm + 8) * crs + gn, v2, v3);
                } else {
                    wr_hl(Chi, Clo, (size_t)gm * crs + (size_t)gn * ccs, v0);
                    wr_hl(Chi, Clo, (size_t)gm * crs + (size_t)(gn + 1) * ccs, v1);
                    wr_hl(Chi, Clo, (size_t)(gm + 8) * crs + (size_t)gn * ccs, v2);
                    wr_hl(Chi, Clo, (size_t)(gm + 8) * crs + (size_t)(gn + 1) * ccs, v3);
                }
            }
        }
    }
}

// ---------------------------------------------------------------------------
// RoPE: q_r (fp32 temp) -> q hi/lo cols 128..191
// ---------------------------------------------------------------------------
__global__ void rope_q_split(const float* __restrict__ qrp, bf16* __restrict__ qhi,
                             bf16* __restrict__ qlo, const float* __restrict__ freqs)
{
    int idx = blockIdx.x * blockDim.x + threadIdx.x;
    if (idx >= NH * TT * 32) return;
    int i = idx & 31;
    int t = (idx >> 5) & (TT - 1);
    int n = idx >> 16;
    const float* src = qrp + ((size_t)n * TT + t) * DRH;
    float fr = freqs[t * 32 + i];
    float c = cosf(fr), s = sinf(fr);
    float re = src[i], im = src[i + 32];
    size_t base = ((size_t)n * TT + t) * HDIM + DHV;
    wr_hl(qhi, qlo, base + i,      re * c - im * s);
    wr_hl(qhi, qlo, base + i + 32, re * s + im * c);
}

__global__ void rope_k_split(const float* __restrict__ krp, bf16* __restrict__ khi,
                             bf16* __restrict__ klo, const float* __restrict__ freqs)
{
    int idx = blockIdx.x * blockDim.x + threadIdx.x;
    if (idx >= TT * 32) return;
    int i = idx & 31;
    int t = idx >> 5;
    float fr = freqs[t * 32 + i];
    float c = cosf(fr), s = sinf(fr);
    float re = krp[t * 64 + i];
    float im = krp[t * 64 + i + 32];
    float o1 = (re * c - im * s) * (1.0f / 16.0f);
    float o2 = (re * s + im * c) * (1.0f / 16.0f);
#pragma unroll
    for (int n = 0; n < NH; n++) {
        size_t base = ((size_t)n * TT + t) * HDIM + DHV;
        wr_hl(khi, klo, base + i, o1);
        wr_hl(khi, klo, base + i + 32, o2);
    }
}

// ---------------------------------------------------------------------------
// Causal softmax; writes S as bf16 hi/lo IN PLACE over the fp32 row:
// row's 8KB = [2048 hi bf16][2048 lo bf16].
// ---------------------------------------------------------------------------
__global__ __launch_bounds__(256)
void softmax_causal_split(float* __restrict__ L)
{
    int row = blockIdx.x;               // n*2048 + t
    int t = row & (TT - 1);
    int nvalid = t + 1;
    float* p = L + (size_t)row * TT;
    int tid = threadIdx.x;
    __shared__ float red[256];

    float v[8];
    float m = -3.4e38f;
#pragma unroll
    for (int k = 0; k < 8; k++) {
        int idx = tid + k * 256;
        v[k] = (idx < nvalid) ? p[idx] : -3.4e38f;
        m = fmaxf(m, v[k]);
    }
    red[tid] = m;
    __syncthreads();
    for (int s = 128; s > 0; s >>= 1) {
        if (tid < s) red[tid] = fmaxf(red[tid], red[tid + s]);
        __syncthreads();
    }
    m = red[0];
    __syncthreads();

    float sum = 0.0f;
#pragma unroll
    for (int k = 0; k < 8; k++) {
        v[k] = expf(v[k] - m);
        sum += v[k];
    }
    red[tid] = sum;
    __syncthreads();
    for (int s = 128; s > 0; s >>= 1) {
        if (tid < s) red[tid] += red[tid + s];
        __syncthreads();
    }
    float inv = 1.0f / red[0];
    __syncthreads();   // all reads of this row complete before aliased writes

    bf16* ph = (bf16*)p;
#pragma unroll
    for (int k = 0; k < 8; k++) {
        int idx = tid + k * 256;
        float val = (idx < nvalid) ? v[k] * inv : 0.0f;
        bf16 h = __float2bfloat16_rn(val);
        ph[idx]        = h;
        ph[2048 + idx] = __float2bfloat16_rn(val - __bfloat162float(h));
    }
}

// ---------------------------------------------------------------------------
extern "C" void kernel_launch(void* const* d_in, const int* in_sizes, int n_in,
                              void* d_out, int out_size)
{
    const float* h      = (const float*)d_in[0];
    const float* freqs  = (const float*)d_in[1];
    const float* w_dkv  = (const float*)d_in[3];
    const float* w_uk   = (const float*)d_in[4];
    const float* w_uv   = (const float*)d_in[5];
    const float* w_dq   = (const float*)d_in[6];
    const float* w_uq   = (const float*)d_in[7];
    const float* w_qr   = (const float*)d_in[8];
    const float* w_kr   = (const float*)d_in[9];
    const float* w_o    = (const float*)d_in[10];
    float* out = (float*)d_out;

    unsigned char* sc = nullptr;
    cudaGetSymbolAddress((void**)&sc, g_scratch);
    bf16* hhi   = (bf16*)(sc + O_HHI);   bf16* hlo   = (bf16*)(sc + O_HLO);
    bf16* wdkvh = (bf16*)(sc + O_WDKVH); bf16* wdkvl = (bf16*)(sc + O_WDKVL);
    bf16* wdqh  = (bf16*)(sc + O_WDQH);  bf16* wdql  = (bf16*)(sc + O_WDQL);
    bf16* wkrh  = (bf16*)(sc + O_WKRH);  bf16* wkrl  = (bf16*)(sc + O_WKRL);
    bf16* wukh  = (bf16*)(sc + O_WUKH);  bf16* wukl  = (bf16*)(sc + O_WUKL);
    bf16* wuvh  = (bf16*)(sc + O_WUVH);  bf16* wuvl  = (bf16*)(sc + O_WUVL);
    bf16* wuqh  = (bf16*)(sc + O_WUQH);  bf16* wuql  = (bf16*)(sc + O_WUQL);
    bf16* wqrh  = (bf16*)(sc + O_WQRH);  bf16* wqrl  = (bf16*)(sc + O_WQRL);
    bf16* woh   = (bf16*)(sc + O_WOH);   bf16* wol   = (bf16*)(sc + O_WOL);
    bf16* ckvh  = (bf16*)(sc + O_CKVH);  bf16* ckvl  = (bf16*)(sc + O_CKVL);
    bf16* cqh   = (bf16*)(sc + O_CQH);   bf16* cql   = (bf16*)(sc + O_CQL);
    bf16* qhi   = (bf16*)(sc + O_QHI);   bf16* qlo   = (bf16*)(sc + O_QLO);
    bf16* khi   = (bf16*)(sc + O_KHI);   bf16* klo   = (bf16*)(sc + O_KLO);
    bf16* vhi   = (bf16*)(sc + O_VHI);   bf16* vlo   = (bf16*)(sc + O_VLO);
    bf16* outah = (bf16*)(sc + O_OUTAH); bf16* outal = (bf16*)(sc + O_OUTAL);
    float* krp  = (float*)(sc + O_KRP);
    float* qrp  = (float*)(sc + O_QRP);
    float* lg   = (float*)(sc + O_LG);
    bf16* Shi   = (bf16*)(sc + O_LG);           // aliased: row = [2048 hi][2048 lo]
    bf16* Slo   = Shi + 2048;

    // dynamic smem: 3 stages * STAGE
    const int SM64  = 3 * (2 * 128 * 80 + 2 * 64 * 80);    //  92160
    const int SM128 = 3 * (2 * 128 * 80 + 2 * 128 * 80);   // 122880
    const int SMT   = 3 * (4 * 32 * 272);                  // 104448
    cudaFuncSetAttribute(hgemm<64, false, false, false, 1>,
                         cudaFuncAttributeMaxDynamicSharedMemorySize, SM64);
    cudaFuncSetAttribute(hgemm<64, false, false, false, 0>,
                         cudaFuncAttributeMaxDynamicSharedMemorySize, SM64);
    cudaFuncSetAttribute(hgemm<128, false, false, false, 1>,
                         cudaFuncAttributeMaxDynamicSharedMemorySize, SM128);
    cudaFuncSetAttribute(hgemm<128, false, true, false, 0>,
                         cudaFuncAttributeMaxDynamicSharedMemorySize, SM128);
    cudaFuncSetAttribute(hgemm<128, true, false, true, 1>,
                         cudaFuncAttributeMaxDynamicSharedMemorySize, SMT);
    cudaFuncSetAttribute(hgemm<128, false, false, false, 0>,
                         cudaFuncAttributeMaxDynamicSharedMemorySize, SM128);

    const float scale = 1.0f / sqrtf((float)HDIM);
    dim3 blk(256);

    // 0) split inputs + weights to bf16 hi/lo (single launch)
    SplitArgs sa;
    sa.src[0] = h;     sa.hi[0] = hhi;   sa.lo[0] = hlo;   sa.n[0] = 2048 * 2048;
    sa.src[1] = w_o;   sa.hi[1] = woh;   sa.lo[1] = wol;   sa.n[1] = 2048 * 2048;
    sa.src[2] = w_dkv; sa.hi[2] = wdkvh; sa.lo[2] = wdkvl; sa.n[2] = 512 * 2048;
    sa.src[3] = w_dq;  sa.hi[3] = wdqh;  sa.lo[3] = wdql;  sa.n[3] = 512 * 2048;
    sa.src[4] = w_uk;  sa.hi[4] = wukh;  sa.lo[4] = wukl;  sa.n[4] = 128 * 16 * 512;
    sa.src[5] = w_uv;  sa.hi[5] = wuvh;  sa.lo[5] = wuvl;  sa.n[5] = 128 * 16 * 512;
    sa.src[6] = w_uq;  sa.hi[6] = wuqh;  sa.lo[6] = wuql;  sa.n[6] = 128 * 16 * 512;
    sa.src[7] = w_qr;  sa.hi[7] = wqrh;  sa.lo[7] = wqrl;  sa.n[7] = 64 * 16 * 512;
    sa.src[8] = w_kr;  sa.hi[8] = wkrh;  sa.lo[8] = wkrl;  sa.n[8] = 64 * 2048;
    split_all_kernel<<<dim3(512, 9), 256>>>(sa);

    // 1) down projections
    hgemm<64, false, false, false, 1><<<dim3(8, 16, 1), blk, SM64>>>(
        hhi, hlo, DD, 0, wdkvh, wdkvl, DD, 0,
        nullptr, ckvh, ckvl, DCC, 1, 0, DD, 1.0f);
    hgemm<64, false, false, false, 1><<<dim3(8, 16, 1), blk, SM64>>>(
        hhi, hlo, DD, 0, wdqh, wdql, DD, 0,
        nullptr, cqh, cql, DCC, 1, 0, DD, 1.0f);
    hgemm<64, false, false, false, 0><<<dim3(1, 16, 1), blk, SM64>>>(
        hhi, hlo, DD, 0, wkrh, wkrl, DD, 0,
        krp, nullptr, nullptr, DRH, 1, 0, DD, 1.0f);

    // 2) per-head up-projections (z = head)
    hgemm<128, false, false, false, 1><<<dim3(1, 16, NH), blk, SM128>>>(
        ckvh, ckvl, DCC, 0, wukh, wukl, NH * DCC, DCC,
        nullptr, khi, klo, HDIM, 1, (long long)TT * HDIM, DCC, 1.0f);
    hgemm<128, false, false, false, 1><<<dim3(1, 16, NH), blk, SM128>>>(
        ckvh, ckvl, DCC, 0, wuvh, wuvl, NH * DCC, DCC,
        nullptr, vhi, vlo, DHV, 1, (long long)TT * DHV, DCC, 1.0f);
    hgemm<128, false, false, false, 1><<<dim3(1, 16, NH), blk, SM128>>>(
        cqh, cql, DCC, 0, wuqh, wuql, NH * DCC, DCC,
        nullptr, qhi, qlo, HDIM, 1, (long long)TT * HDIM, DCC, 1.0f);
    hgemm<64, false, false, false, 0><<<dim3(1, 16, NH), blk, SM64>>>(
        cqh, cql, DCC, 0, wqrh, wqrl, NH * DCC, DCC,
        qrp, nullptr, nullptr, DRH, 1, (long long)TT * DRH, DCC, 1.0f);

    // 3) RoPE -> q/k hi/lo cols 128..191
    rope_q_split<<<(NH * TT * 32 + 255) / 256, 256>>>(qrp, qhi, qlo, freqs);
    rope_k_split<<<(TT * 32 + 255) / 256, 256>>>(krp, khi, klo, freqs);

    // 4) logits = q k^T * scale (lower-triangle tiles; 136 per head)
    hgemm<128, false, true, false, 0><<<dim3(136, 1, NH), blk, SM128>>>(
        qhi, qlo, HDIM, (long long)TT * HDIM, khi, klo, HDIM, (long long)TT * HDIM,
        lg, nullptr, nullptr, TT, 1, (long long)TT * TT, HDIM, scale);

    // 5) causal softmax; emits S as bf16 hi/lo in place
    softmax_causal_split<<<NH * TT, 256>>>(lg);

    // 6) out[l,e] = sum_t S[t,l] V[t,e]; trans staging + ldmatrix.trans
    hgemm<128, true, false, true, 1><<<dim3(1, 16, NH), blk, SMT>>>(
        Shi, Slo, 2 * TT, (long long)TT * 2 * TT, vhi, vlo, DHV, (long long)TT * DHV,
        nullptr, outah, outal, DD, NH, 1, TT, 1.0f);

    // 7) final = outa . w_o^T (both bf16 hi/lo), fp32 out
    hgemm<128, false, false, false, 0><<<dim3(16, 16, 1), blk, SM128>>>(
        outah, outal, DD, 0, woh, wol, DD, 0,
        out, nullptr, nullptr, DD, 1, 0, DD, 1.0f);
}

// round 13
// speedup vs baseline: 1.8143x; 1.1023x over previous
#include <cuda_runtime.h>
#include <cuda_bf16.h>
#include <math.h>
#include <stdint.h>

#define TT 2048
#define DD 2048
#define NH 16
#define DHV 128
#define DRH 64
#define DCC 512
#define HDIM 192

typedef __nv_bfloat16 bf16;

// ---------------------------------------------------------------------------
// Scratch layout (bytes). bf16 tensors come as hi/lo pairs.
// ---------------------------------------------------------------------------
#define S_H     (2048ULL*2048*2)
#define S_WDKV  (512ULL*2048*2)
#define S_WDQ   (512ULL*2048*2)
#define S_WKR   (64ULL*2048*2)
#define S_WUK   (128ULL*16*512*2)
#define S_WUV   (128ULL*16*512*2)
#define S_WUQ   (128ULL*16*512*2)
#define S_WQR   (64ULL*16*512*2)
#define S_WO    (2048ULL*2048*2)
#define S_CKV   (2048ULL*512*2)
#define S_CQ    (2048ULL*512*2)
#define S_Q     (16ULL*2048*192*2)
#define S_K     (16ULL*2048*192*2)
#define S_V     (16ULL*2048*128*2)
#define S_OUTA  (2048ULL*2048*2)
#define S_KRP   (2048ULL*64*4)
#define S_QRP   (16ULL*2048*64*4)
#define S_LG    (16ULL*2048*2048*4)

#define O_HHI   0ULL
#define O_HLO   (O_HHI+S_H)
#define O_WDKVH (O_HLO+S_H)
#define O_WDKVL (O_WDKVH+S_WDKV)
#define O_WDQH  (O_WDKVL+S_WDKV)
#define O_WDQL  (O_WDQH+S_WDQ)
#define O_WKRH  (O_WDQL+S_WDQ)
#define O_WKRL  (O_WKRH+S_WKR)
#define O_WUKH  (O_WKRL+S_WKR)
#define O_WUKL  (O_WUKH+S_WUK)
#define O_WUVH  (O_WUKL+S_WUK)
#define O_WUVL  (O_WUVH+S_WUV)
#define O_WUQH  (O_WUVL+S_WUV)
#define O_WUQL  (O_WUQH+S_WUQ)
#define O_WQRH  (O_WUQL+S_WUQ)
#define O_WQRL  (O_WQRH+S_WQR)
#define O_WOH   (O_WQRL+S_WQR)
#define O_WOL   (O_WOH+S_WO)
#define O_CKVH  (O_WOL+S_WO)
#define O_CKVL  (O_CKVH+S_CKV)
#define O_CQH   (O_CKVL+S_CKV)
#define O_CQL   (O_CQH+S_CQ)
#define O_QHI   (O_CQL+S_CQ)
#define O_QLO   (O_QHI+S_Q)
#define O_KHI   (O_QLO+S_Q)
#define O_KLO   (O_KHI+S_K)
#define O_VHI   (O_KLO+S_K)
#define O_VLO   (O_VHI+S_V)
#define O_OUTAH (O_VLO+S_V)
#define O_OUTAL (O_OUTAH+S_OUTA)
#define O_KRP   (O_OUTAL+S_OUTA)
#define O_QRP   (O_KRP+S_KRP)
#define O_LG    (O_QRP+S_QRP)
#define SCRATCH_BYTES (O_LG+S_LG)

__device__ __align__(256) unsigned char g_scratch[SCRATCH_BYTES];

// ---------------------------------------------------------------------------
__device__ __forceinline__ uint32_t smem_u32(const void* p) {
    uint32_t a;
    asm("{ .reg .u64 t; cvta.to.shared.u64 t, %1; cvt.u32.u64 %0, t; }"
        : "=r"(a) : "l"(p));
    return a;
}
__device__ __forceinline__ void ldmx4(uint32_t* r, uint32_t addr) {
    asm volatile("ldmatrix.sync.aligned.m8n8.x4.shared.b16 {%0,%1,%2,%3}, [%4];"
                 : "=r"(r[0]), "=r"(r[1]), "=r"(r[2]), "=r"(r[3]) : "r"(addr));
}
__device__ __forceinline__ void ldmx4t(uint32_t* r, uint32_t addr) {
    asm volatile("ldmatrix.sync.aligned.m8n8.x4.trans.shared.b16 {%0,%1,%2,%3}, [%4];"
                 : "=r"(r[0]), "=r"(r[1]), "=r"(r[2]), "=r"(r[3]) : "r"(addr));
}
__device__ __forceinline__ void mma16816(float* c, const uint32_t* a,
                                         uint32_t b0, uint32_t b1) {
    asm volatile(
        "mma.sync.aligned.m16n8k16.row.col.f32.bf16.bf16.f32 "
        "{%0,%1,%2,%3}, {%4,%5,%6,%7}, {%8,%9}, {%0,%1,%2,%3};"
        : "+f"(c[0]), "+f"(c[1]), "+f"(c[2]), "+f"(c[3])
        : "r"(a[0]), "r"(a[1]), "r"(a[2]), "r"(a[3]), "r"(b0), "r"(b1));
}
__device__ __forceinline__ uint32_t bf2_u32(__nv_bfloat162 v) {
    return *reinterpret_cast<uint32_t*>(&v);
}
#define CP16(d, s) asm volatile("cp.async.cg.shared.global [%0], [%1], 16;" \
                                :: "r"(d), "l"(s))
#define CP_COMMIT() asm volatile("cp.async.commit_group;" ::: "memory")
#define CP_WAIT1()  asm volatile("cp.async.wait_group 1;" ::: "memory")
#define CP_WAIT0()  asm volatile("cp.async.wait_group 0;" ::: "memory")

__device__ __forceinline__ void wr_hl(bf16* hi, bf16* lo, size_t o, float v) {
    bf16 h = __float2bfloat16_rn(v);
    hi[o] = h;
    lo[o] = __float2bfloat16_rn(v - __bfloat162float(h));
}
__device__ __forceinline__ void wr_hl2(bf16* hi, bf16* lo, size_t o,
                                       float v0, float v1) {
    __nv_bfloat162 h = __floats2bfloat162_rn(v0, v1);
    float2 f = __bfloat1622float2(h);
    __nv_bfloat162 l = __floats2bfloat162_rn(v0 - f.x, v1 - f.y);
    *(uint32_t*)(hi + o) = bf2_u32(h);
    *(uint32_t*)(lo + o) = bf2_u32(l);
}

// ---------------------------------------------------------------------------
// Fused fp32 -> bf16 hi/lo split for all 9 tensors (one launch).
// ---------------------------------------------------------------------------
struct SplitArgs {
    const float* src[9];
    bf16* hi[9];
    bf16* lo[9];
    int n[9];
};

__global__ void split_all_kernel(SplitArgs a)
{
    int z = blockIdx.y;
    const float* __restrict__ src = a.src[z];
    bf16* __restrict__ hi = a.hi[z];
    bf16* __restrict__ lo = a.lo[z];
    int n = a.n[z];
    int stride = gridDim.x * blockDim.x * 4;
    for (int i = (blockIdx.x * blockDim.x + threadIdx.x) * 4; i < n; i += stride) {
        float4 v = *(const float4*)(src + i);
        __nv_bfloat162 h0 = __floats2bfloat162_rn(v.x, v.y);
        __nv_bfloat162 h1 = __floats2bfloat162_rn(v.z, v.w);
        float2 f0 = __bfloat1622float2(h0);
        float2 f1 = __bfloat1622float2(h1);
        __nv_bfloat162 l0 = __floats2bfloat162_rn(v.x - f0.x, v.y - f0.y);
        __nv_bfloat162 l1 = __floats2bfloat162_rn(v.z - f1.x, v.w - f1.y);
        *(uint2*)(hi + i) = make_uint2(bf2_u32(h0), bf2_u32(h1));
        *(uint2*)(lo + i) = make_uint2(bf2_u32(l0), bf2_u32(l1));
    }
}

// ---------------------------------------------------------------------------
// Segment descriptor for the fused projection GEMM.
// ---------------------------------------------------------------------------
struct Seg {
    const bf16* Bhi; const bf16* Blo;
    int ldb; long long strB;           // B row stride / per-z offset
    float* Cf; bf16* Chi; bf16* Clo;   // output (epi selects)
    long long crs, strC;               // C row stride / per-z offset
    int epi;                           // 0 = fp32, 1 = bf16 hi/lo
};

// ---------------------------------------------------------------------------
// Fused multi-segment projection GEMM. M-tile=128, N-tile=64, BK=32,
// 3-stage cp.async pipeline, 2 CTAs/SM. C = sum_k A[m,k]*B[n,k] routed
// per n-tile into up to 3 segments. All outputs row-contiguous (ccs=1).
// Tile boundaries: seg0 tiles [0,t1), seg1 [t1,t2), seg2 [t2,inf).
// ---------------------------------------------------------------------------
__global__ __launch_bounds__(256, 2)
void hgemm_fused(const bf16* __restrict__ Ahi, const bf16* __restrict__ Alo,
                 int lda, long long strA,
                 Seg s0, Seg s1, Seg s2, int t1, int t2, int K)
{
    constexpr int AB = 128 * 80, BB = 64 * 80;
    constexpr int oAL = AB, oBH = 2 * AB;
    constexpr int STAGE = 2 * AB + 2 * BB;   // 30720

    extern __shared__ char smarr[];
    const uint32_t smb = smem_u32(smarr);
    const int tid = threadIdx.x, wid = tid >> 5, lane = tid & 31;
    const int z = blockIdx.z;
    const int nt = blockIdx.x;
    const int m0 = blockIdx.y * 128;

    Seg sg = (nt < t1) ? s0 : (nt < t2) ? s1 : s2;
    const int base = (nt < t1) ? 0 : (nt < t2) ? t1 : t2;
    const int n0 = (nt - base) * 64;

    const bf16* Bh = sg.Bhi + (size_t)z * (size_t)sg.strB;
    const bf16* Bl = sg.Blo + (size_t)z * (size_t)sg.strB;
    Ahi += (size_t)z * (size_t)strA;  Alo += (size_t)z * (size_t)strA;

    const int niter = K / 32;

    auto issue = [&](int it) {
        const int kk0 = it * 32;
        const uint32_t sb = smb + (it % 3) * STAGE;
#pragma unroll
        for (int c = tid; c < 512; c += 256) {
            int row = c >> 2, kc = (c & 3) * 8;
            uint32_t d = sb + row * 80 + kc * 2;
            const bf16* s = Ahi + (size_t)(m0 + row) * lda + kk0 + kc;
            CP16(d, s);
            CP16(d + oAL, Alo + (s - Ahi));
        }
        {
            int c = tid;   // 256 chunks = 64 rows * 4
            int row = c >> 2, kc = (c & 3) * 8;
            uint32_t d = sb + oBH + row * 80 + kc * 2;
            const bf16* s = Bh + (size_t)(n0 + row) * sg.ldb + kk0 + kc;
            CP16(d, s);
            CP16(d + BB, Bl + (s - Bh));
        }
    };

    float acc[2][4][4];
#pragma unroll
    for (int a = 0; a < 2; a++)
#pragma unroll
        for (int b = 0; b < 4; b++)
#pragma unroll
            for (int c = 0; c < 4; c++) acc[a][b][c] = 0.0f;

    const int wm  = (wid & 3) * 32;
    const int wnb = (wid >> 2) * 32;   // WN=32

    issue(0); CP_COMMIT();
    if (niter > 1) { issue(1); CP_COMMIT(); }

    for (int it = 0; it < niter; it++) {
        if (it + 1 < niter) CP_WAIT1(); else CP_WAIT0();
        __syncthreads();
        if (it + 2 < niter) { issue(it + 2); CP_COMMIT(); }

        const uint32_t sb = smb + (it % 3) * STAGE;
#pragma unroll
        for (int kk = 0; kk < 32; kk += 16) {
            uint32_t ah[2][4], al[2][4];
#pragma unroll
            for (int mt = 0; mt < 2; mt++) {
                int r = wm + mt * 16 + (lane & 15);
                uint32_t a = sb + r * 80 + kk * 2 + ((lane >> 4) << 4);
                ldmx4(ah[mt], a);
                ldmx4(al[mt], a + oAL);
            }
#pragma unroll
            for (int ng = 0; ng < 2; ng++) {   // NG = WN/16 = 2
                uint32_t bh[4], bl[4];
                int r = wnb + ng * 16 + (lane & 15);
                uint32_t a = sb + oBH + r * 80 + kk * 2 + ((lane >> 4) << 4);
                ldmx4(bh, a);
                ldmx4(bl, a + BB);
#pragma unroll
                for (int hf = 0; hf < 2; hf++) {
#pragma unroll
                    for (int mt = 0; mt < 2; mt++) {
                        float* c = acc[mt][ng * 2 + hf];
                        mma16816(c, ah[mt], bh[hf], bh[hf + 2]);
                        mma16816(c, ah[mt], bl[hf], bl[hf + 2]);
                        mma16816(c, al[mt], bh[hf], bh[hf + 2]);
                    }
                }
            }
        }
        __syncthreads();
    }

    // Epilogue (ccs == 1 for all segments)
    float* Cf = sg.Cf + (size_t)z * (size_t)(sg.epi == 0 ? sg.strC : 0);
    bf16* Chi = sg.Chi + (size_t)z * (size_t)(sg.epi == 1 ? sg.strC : 0);
    bf16* Clo = sg.Clo + (size_t)z * (size_t)(sg.epi == 1 ? sg.strC : 0);
#pragma unroll
    for (int mt = 0; mt < 2; mt++) {
#pragma unroll
        for (int nt8 = 0; nt8 < 4; nt8++) {
            int gm = m0 + wm + mt * 16 + (lane >> 2);
            int gn = n0 + wnb + nt8 * 8 + (lane & 3) * 2;
            float v0 = acc[mt][nt8][0];
            float v1 = acc[mt][nt8][1];
            float v2 = acc[mt][nt8][2];
            float v3 = acc[mt][nt8][3];
            if (sg.epi == 0) {
                *(float2*)&Cf[(size_t)gm * sg.crs + gn]       = make_float2(v0, v1);
                *(float2*)&Cf[(size_t)(gm + 8) * sg.crs + gn] = make_float2(v2, v3);
            } else {
                wr_hl2(Chi, Clo, (size_t)gm * sg.crs + gn, v0, v1);
                wr_hl2(Chi, Clo, (size_t)(gm + 8) * sg.crs + gn, v2, v3);
            }
        }
    }
}

// ---------------------------------------------------------------------------
// HMMA GEMM (NTILE=128), pre-split bf16 hi/lo, 3-stage cp.async pipeline.
// TRANS: A,B k-major in gmem; ldmatrix.trans. TRI: lower-tri tile grid.
// CK: k starts at m0. EPI: 0 = fp32 out (alpha), 1 = bf16 hi/lo out.
// ---------------------------------------------------------------------------
template<bool TRANS, bool TRI, bool CK, int EPI>
__global__ __launch_bounds__(256, 1)
void hgemm(const bf16* __restrict__ Ahi, const bf16* __restrict__ Alo,
           int lda, long long strA,
           const bf16* __restrict__ Bhi, const bf16* __restrict__ Blo,
           int ldb, long long strB,
           float* __restrict__ Cf, bf16* __restrict__ Chi, bf16* __restrict__ Clo,
           long long crs, long long ccs, long long strC,
           int K, float alpha)
{
    constexpr int NTILE = 128;
    constexpr int WN  = 64;
    constexpr int NT8 = 8;
    constexpr int NG  = 4;
    constexpr int AB  = TRANS ? 32 * 272 : 128 * 80;
    constexpr int BB  = TRANS ? 32 * 272 : NTILE * 80;
    constexpr int oAL = AB, oBH = 2 * AB;
    constexpr int STAGE = 2 * AB + 2 * BB;

    extern __shared__ char smarr[];
    const uint32_t smb = smem_u32(smarr);
    const int tid = threadIdx.x, wid = tid >> 5, lane = tid & 31;
    const int z = blockIdx.z;
    Ahi += (size_t)z * (size_t)strA;  Alo += (size_t)z * (size_t)strA;
    Bhi += (size_t)z * (size_t)strB;  Blo += (size_t)z * (size_t)strB;
    if (EPI == 0) { Cf += (size_t)z * (size_t)strC; }
    else { Chi += (size_t)z * (size_t)strC; Clo += (size_t)z * (size_t)strC; }

    int m0, n0;
    if (TRI) {
        int x = blockIdx.x;
        int tm = (int)((sqrtf(8.0f * x + 1.0f) - 1.0f) * 0.5f);
        while ((tm + 1) * (tm + 2) / 2 <= x) tm++;
        while (tm * (tm + 1) / 2 > x) tm--;
        int tn = x - tm * (tm + 1) / 2;
        m0 = tm * 128; n0 = tn * 128;
    } else {
        m0 = blockIdx.y * 128;
        n0 = blockIdx.x * NTILE;
    }

    const int kbeg  = CK ? m0 : 0;
    const int niter = (K - kbeg) / 32;

    auto issue = [&](int it) {
        const int kk0 = kbeg + it * 32;
        const uint32_t sb = smb + (it % 3) * STAGE;
        if (!TRANS) {
#pragma unroll
            for (int c = tid; c < 512; c += 256) {
                int row = c >> 2, kc = (c & 3) * 8;
                uint32_t d = sb + row * 80 + kc * 2;
                const bf16* s = Ahi + (size_t)(m0 + row) * lda + kk0 + kc;
                CP16(d, s);
                CP16(d + oAL, Alo + (s - Ahi));
            }
#pragma unroll
            for (int c = tid; c < NTILE * 4; c += 256) {
                int row = c >> 2, kc = (c & 3) * 8;
                uint32_t d = sb + oBH + row * 80 + kc * 2;
                const bf16* s = Bhi + (size_t)(n0 + row) * ldb + kk0 + kc;
                CP16(d, s);
                CP16(d + BB, Blo + (s - Bhi));
            }
        } else {
#pragma unroll
            for (int c = tid; c < 512; c += 256) {
                int kr = c >> 4, mc = (c & 15) * 8;
                uint32_t d = sb + kr * 272 + mc * 2;
                const bf16* s = Ahi + (size_t)(kk0 + kr) * lda + m0 + mc;
                CP16(d, s);
                CP16(d + oAL, Alo + (s - Ahi));
            }
#pragma unroll
            for (int c = tid; c < 512; c += 256) {
                int kr = c >> 4, nc = (c & 15) * 8;
                uint32_t d = sb + oBH + kr * 272 + nc * 2;
                const bf16* s = Bhi + (size_t)(kk0 + kr) * ldb + n0 + nc;
                CP16(d, s);
                CP16(d + BB, Blo + (s - Bhi));
            }
        }
    };

    float acc[2][NT8][4];
#pragma unroll
    for (int a = 0; a < 2; a++)
#pragma unroll
        for (int b = 0; b < NT8; b++)
#pragma unroll
            for (int c = 0; c < 4; c++) acc[a][b][c] = 0.0f;

    const int wm  = (wid & 3) * 32;
    const int wnb = (wid >> 2) * WN;

    issue(0); CP_COMMIT();
    if (niter > 1) { issue(1); CP_COMMIT(); }

    for (int it = 0; it < niter; it++) {
        if (it + 1 < niter) CP_WAIT1(); else CP_WAIT0();
        __syncthreads();
        if (it + 2 < niter) { issue(it + 2); CP_COMMIT(); }

        const uint32_t sb = smb + (it % 3) * STAGE;
#pragma unroll
        for (int kk = 0; kk < 32; kk += 16) {
            uint32_t ah[2][4], al[2][4];
#pragma unroll
            for (int mt = 0; mt < 2; mt++) {
                if (!TRANS) {
                    int r = wm + mt * 16 + (lane & 15);
                    uint32_t a = sb + r * 80 + kk * 2 + ((lane >> 4) << 4);
                    ldmx4(ah[mt], a);
                    ldmx4(al[mt], a + oAL);
                } else {
                    int kr = kk + ((lane >> 4) << 3) + (lane & 7);
                    int mc = wm + mt * 16 + ((lane >> 3) & 1) * 8;
                    uint32_t a = sb + kr * 272 + mc * 2;
                    ldmx4t(ah[mt], a);
                    ldmx4t(al[mt], a + oAL);
                }
            }
#pragma unroll
            for (int ng = 0; ng < NG; ng++) {
                uint32_t bh[4], bl[4];
                if (!TRANS) {
                    int r = wnb + ng * 16 + (lane & 15);
                    uint32_t a = sb + oBH + r * 80 + kk * 2 + ((lane >> 4) << 4);
                    ldmx4(bh, a);
                    ldmx4(bl, a + BB);
                } else {
                    int kr = kk + ((lane >> 4) << 3) + (lane & 7);
                    int nc = wnb + ng * 16 + ((lane >> 3) & 1) * 8;
                    uint32_t a = sb + oBH + kr * 272 + nc * 2;
                    ldmx4t(bh, a);
                    ldmx4t(bl, a + BB);
                }
#pragma unroll
                for (int hf = 0; hf < 2; hf++) {
#pragma unroll
                    for (int mt = 0; mt < 2; mt++) {
                        float* c = acc[mt][ng * 2 + hf];
                        mma16816(c, ah[mt], bh[hf], bh[hf + 2]);
                        mma16816(c, ah[mt], bl[hf], bl[hf + 2]);
                        mma16816(c, al[mt], bh[hf], bh[hf + 2]);
                    }
                }
            }
        }
        __syncthreads();
    }

#pragma unroll
    for (int mt = 0; mt < 2; mt++) {
#pragma unroll
        for (int nt = 0; nt < NT8; nt++) {
            int gm = m0 + wm + mt * 16 + (lane >> 2);
            int gn = n0 + wnb + nt * 8 + (lane & 3) * 2;
            float v0 = acc[mt][nt][0] * alpha;
            float v1 = acc[mt][nt][1] * alpha;
            float v2 = acc[mt][nt][2] * alpha;
            float v3 = acc[mt][nt][3] * alpha;
            if (EPI == 0) {
                if (ccs == 1) {
                    *(float2*)&Cf[(size_t)gm * crs + gn]       = make_float2(v0, v1);
                    *(float2*)&Cf[(size_t)(gm + 8) * crs + gn] = make_float2(v2, v3);
                } else {
                    Cf[(size_t)gm * crs + (size_t)gn * ccs]             = v0;
                    Cf[(size_t)gm * crs + (size_t)(gn + 1) * ccs]       = v1;
                    Cf[(size_t)(gm + 8) * crs + (size_t)gn * ccs]       = v2;
                    Cf[(size_t)(gm + 8) * crs + (size_t)(gn + 1) * ccs] = v3;
                }
            } else {
                if (ccs == 1) {
                    wr_hl2(Chi, Clo, (size_t)gm * crs + gn, v0, v1);
                    wr_hl2(Chi, Clo, (size_t)(gm + 8) * crs + gn, v2, v3);
                } else {
                    wr_hl(Chi, Clo, (size_t)gm * crs + (size_t)gn * ccs, v0);
                    wr_hl(Chi, Clo, (size_t)gm * crs + (size_t)(gn + 1) * ccs, v1);
                    wr_hl(Chi, Clo, (size_t)(gm + 8) * crs + (size_t)gn * ccs, v2);
                    wr_hl(Chi, Clo, (size_t)(gm + 8) * crs + (size_t)(gn + 1) * ccs, v3);
                }
            }
        }
    }
}

// ---------------------------------------------------------------------------
// RoPE: q_r (fp32 temp) -> q hi/lo cols 128..191
// ---------------------------------------------------------------------------
__global__ void rope_q_split(const float* __restrict__ qrp, bf16* __restrict__ qhi,
                             bf16* __restrict__ qlo, const float* __restrict__ freqs)
{
    int idx = blockIdx.x * blockDim.x + threadIdx.x;
    if (idx >= NH * TT * 32) return;
    int i = idx & 31;
    int t = (idx >> 5) & (TT - 1);
    int n = idx >> 16;
    const float* src = qrp + ((size_t)n * TT + t) * DRH;
    float fr = freqs[t * 32 + i];
    float c = cosf(fr), s = sinf(fr);
    float re = src[i], im = src[i + 32];
    size_t base = ((size_t)n * TT + t) * HDIM + DHV;
    wr_hl(qhi, qlo, base + i,      re * c - im * s);
    wr_hl(qhi, qlo, base + i + 32, re * s + im * c);
}

__global__ void rope_k_split(const float* __restrict__ krp, bf16* __restrict__ khi,
                             bf16* __restrict__ klo, const float* __restrict__ freqs)
{
    int idx = blockIdx.x * blockDim.x + threadIdx.x;
    if (idx >= TT * 32) return;
    int i = idx & 31;
    int t = idx >> 5;
    float fr = freqs[t * 32 + i];
    float c = cosf(fr), s = sinf(fr);
    float re = krp[t * 64 + i];
    float im = krp[t * 64 + i + 32];
    float o1 = (re * c - im * s) * (1.0f / 16.0f);
    float o2 = (re * s + im * c) * (1.0f / 16.0f);
#pragma unroll
    for (int n = 0; n < NH; n++) {
        size_t base = ((size_t)n * TT + t) * HDIM + DHV;
        wr_hl(khi, klo, base + i, o1);
        wr_hl(khi, klo, base + i + 32, o2);
    }
}

// ---------------------------------------------------------------------------
// Causal softmax; writes S as bf16 hi/lo IN PLACE over the fp32 row:
// row's 8KB = [2048 hi bf16][2048 lo bf16].
// ---------------------------------------------------------------------------
__global__ __launch_bounds__(256)
void softmax_causal_split(float* __restrict__ L)
{
    int row = blockIdx.x;               // n*2048 + t
    int t = row & (TT - 1);
    int nvalid = t + 1;
    float* p = L + (size_t)row * TT;
    int tid = threadIdx.x;
    __shared__ float red[256];

    float v[8];
    float m = -3.4e38f;
#pragma unroll
    for (int k = 0; k < 8; k++) {
        int idx = tid + k * 256;
        v[k] = (idx < nvalid) ? p[idx] : -3.4e38f;
        m = fmaxf(m, v[k]);
    }
    red[tid] = m;
    __syncthreads();
    for (int s = 128; s > 0; s >>= 1) {
        if (tid < s) red[tid] = fmaxf(red[tid], red[tid + s]);
        __syncthreads();
    }
    m = red[0];
    __syncthreads();

    float sum = 0.0f;
#pragma unroll
    for (int k = 0; k < 8; k++) {
        v[k] = expf(v[k] - m);
        sum += v[k];
    }
    red[tid] = sum;
    __syncthreads();
    for (int s = 128; s > 0; s >>= 1) {
        if (tid < s) red[tid] += red[tid + s];
        __syncthreads();
    }
    float inv = 1.0f / red[0];
    __syncthreads();   // all reads of this row complete before aliased writes

    bf16* ph = (bf16*)p;
#pragma unroll
    for (int k = 0; k < 8; k++) {
        int idx = tid + k * 256;
        float val = (idx < nvalid) ? v[k] * inv : 0.0f;
        bf16 h = __float2bfloat16_rn(val);
        ph[idx]        = h;
        ph[2048 + idx] = __float2bfloat16_rn(val - __bfloat162float(h));
    }
}

// ---------------------------------------------------------------------------
extern "C" void kernel_launch(void* const* d_in, const int* in_sizes, int n_in,
                              void* d_out, int out_size)
{
    const float* h      = (const float*)d_in[0];
    const float* freqs  = (const float*)d_in[1];
    const float* w_dkv  = (const float*)d_in[3];
    const float* w_uk   = (const float*)d_in[4];
    const float* w_uv   = (const float*)d_in[5];
    const float* w_dq   = (const float*)d_in[6];
    const float* w_uq   = (const float*)d_in[7];
    const float* w_qr   = (const float*)d_in[8];
    const float* w_kr   = (const float*)d_in[9];
    const float* w_o    = (const float*)d_in[10];
    float* out = (float*)d_out;

    unsigned char* sc = nullptr;
    cudaGetSymbolAddress((void**)&sc, g_scratch);
    bf16* hhi   = (bf16*)(sc + O_HHI);   bf16* hlo   = (bf16*)(sc + O_HLO);
    bf16* wdkvh = (bf16*)(sc + O_WDKVH); bf16* wdkvl = (bf16*)(sc + O_WDKVL);
    bf16* wdqh  = (bf16*)(sc + O_WDQH);  bf16* wdql  = (bf16*)(sc + O_WDQL);
    bf16* wkrh  = (bf16*)(sc + O_WKRH);  bf16* wkrl  = (bf16*)(sc + O_WKRL);
    bf16* wukh  = (bf16*)(sc + O_WUKH);  bf16* wukl  = (bf16*)(sc + O_WUKL);
    bf16* wuvh  = (bf16*)(sc + O_WUVH);  bf16* wuvl  = (bf16*)(sc + O_WUVL);
    bf16* wuqh  = (bf16*)(sc + O_WUQH);  bf16* wuql  = (bf16*)(sc + O_WUQL);
    bf16* wqrh  = (bf16*)(sc + O_WQRH);  bf16* wqrl  = (bf16*)(sc + O_WQRL);
    bf16* woh   = (bf16*)(sc + O_WOH);   bf16* wol   = (bf16*)(sc + O_WOL);
    bf16* ckvh  = (bf16*)(sc + O_CKVH);  bf16* ckvl  = (bf16*)(sc + O_CKVL);
    bf16* cqh   = (bf16*)(sc + O_CQH);   bf16* cql   = (bf16*)(sc + O_CQL);
    bf16* qhi   = (bf16*)(sc + O_QHI);   bf16* qlo   = (bf16*)(sc + O_QLO);
    bf16* khi   = (bf16*)(sc + O_KHI);   bf16* klo   = (bf16*)(sc + O_KLO);
    bf16* vhi   = (bf16*)(sc + O_VHI);   bf16* vlo   = (bf16*)(sc + O_VLO);
    bf16* outah = (bf16*)(sc + O_OUTAH); bf16* outal = (bf16*)(sc + O_OUTAL);
    float* krp  = (float*)(sc + O_KRP);
    float* qrp  = (float*)(sc + O_QRP);
    float* lg   = (float*)(sc + O_LG);
    bf16* Shi   = (bf16*)(sc + O_LG);           // aliased: row = [2048 hi][2048 lo]
    bf16* Slo   = Shi + 2048;

    const int SMF   = 3 * (2 * 128 * 80 + 2 * 64 * 80);    //  92160 (fused)
    const int SM128 = 3 * (2 * 128 * 80 + 2 * 128 * 80);   // 122880
    const int SMT   = 3 * (4 * 32 * 272);                  // 104448
    cudaFuncSetAttribute(hgemm_fused,
                         cudaFuncAttributeMaxDynamicSharedMemorySize, SMF);
    cudaFuncSetAttribute(hgemm<false, true, false, 0>,
                         cudaFuncAttributeMaxDynamicSharedMemorySize, SM128);
    cudaFuncSetAttribute(hgemm<true, false, true, 1>,
                         cudaFuncAttributeMaxDynamicSharedMemorySize, SMT);
    cudaFuncSetAttribute(hgemm<false, false, false, 0>,
                         cudaFuncAttributeMaxDynamicSharedMemorySize, SM128);

    const float scale = 1.0f / sqrtf((float)HDIM);
    dim3 blk(256);

    // 0) split inputs + weights to bf16 hi/lo (single launch)
    SplitArgs sa;
    sa.src[0] = h;     sa.hi[0] = hhi;   sa.lo[0] = hlo;   sa.n[0] = 2048 * 2048;
    sa.src[1] = w_o;   sa.hi[1] = woh;   sa.lo[1] = wol;   sa.n[1] = 2048 * 2048;
    sa.src[2] = w_dkv; sa.hi[2] = wdkvh; sa.lo[2] = wdkvl; sa.n[2] = 512 * 2048;
    sa.src[3] = w_dq;  sa.hi[3] = wdqh;  sa.lo[3] = wdql;  sa.n[3] = 512 * 2048;
    sa.src[4] = w_uk;  sa.hi[4] = wukh;  sa.lo[4] = wukl;  sa.n[4] = 128 * 16 * 512;
    sa.src[5] = w_uv;  sa.hi[5] = wuvh;  sa.lo[5] = wuvl;  sa.n[5] = 128 * 16 * 512;
    sa.src[6] = w_uq;  sa.hi[6] = wuqh;  sa.lo[6] = wuql;  sa.n[6] = 128 * 16 * 512;
    sa.src[7] = w_qr;  sa.hi[7] = wqrh;  sa.lo[7] = wqrl;  sa.n[7] = 64 * 16 * 512;
    sa.src[8] = w_kr;  sa.hi[8] = wkrh;  sa.lo[8] = wkrl;  sa.n[8] = 64 * 2048;
    split_all_kernel<<<dim3(512, 9), 256>>>(sa);

    Seg zseg = {};   // unused-slot placeholder

    // 1) fused down projection: h x [w_dkv | w_dq | w_kr]  (17 n-tiles)
    {
        Seg sdkv = { wdkvh, wdkvl, DD, 0, nullptr, ckvh, ckvl, DCC, 0, 1 };
        Seg sdq  = { wdqh,  wdql,  DD, 0, nullptr, cqh,  cql,  DCC, 0, 1 };
        Seg skr  = { wkrh,  wkrl,  DD, 0, krp, nullptr, nullptr, DRH, 0, 0 };
        hgemm_fused<<<dim3(17, 16, 1), blk, SMF>>>(
            hhi, hlo, DD, 0, sdkv, sdq, skr, 8, 16, DD);
    }

    // 2) fused q up-projection per head: c_q x [w_uq | w_qr]  (3 n-tiles)
    {
        Seg suq = { wuqh, wuql, NH * DCC, DCC,
                    nullptr, qhi, qlo, HDIM, (long long)TT * HDIM, 1 };
        Seg sqr = { wqrh, wqrl, NH * DCC, DCC,
                    qrp, nullptr, nullptr, DRH, (long long)TT * DRH, 0 };
        hgemm_fused<<<dim3(3, 16, NH), blk, SMF>>>(
            cqh, cql, DCC, 0, suq, sqr, zseg, 2, 3, DCC);
    }

    // 3) fused kv up-projection per head: c_kv x [w_uk | w_uv]  (4 n-tiles)
    //    (launch #4 => this is what ncu captures)
    {
        Seg suk = { wukh, wukl, NH * DCC, DCC,
                    nullptr, khi, klo, HDIM, (long long)TT * HDIM, 1 };
        Seg suv = { wuvh, wuvl, NH * DCC, DCC,
                    nullptr, vhi, vlo, DHV, (long long)TT * DHV, 1 };
        hgemm_fused<<<dim3(4, 16, NH), blk, SMF>>>(
            ckvh, ckvl, DCC, 0, suk, suv, zseg, 2, 4, DCC);
    }

    // 4) RoPE -> q/k hi/lo cols 128..191
    rope_q_split<<<(NH * TT * 32 + 255) / 256, 256>>>(qrp, qhi, qlo, freqs);
    rope_k_split<<<(TT * 32 + 255) / 256, 256>>>(krp, khi, klo, freqs);

    // 5) logits = q k^T * scale (lower-triangle tiles; 136 per head)
    hgemm<false, true, false, 0><<<dim3(136, 1, NH), blk, SM128>>>(
        qhi, qlo, HDIM, (long long)TT * HDIM, khi, klo, HDIM, (long long)TT * HDIM,
        lg, nullptr, nullptr, TT, 1, (long long)TT * TT, HDIM, scale);

    // 6) causal softmax; emits S as bf16 hi/lo in place
    softmax_causal_split<<<NH * TT, 256>>>(lg);

    // 7) out[l,e] = sum_t S[t,l] V[t,e]; trans staging + ldmatrix.trans
    hgemm<true, false, true, 1><<<dim3(1, 16, NH), blk, SMT>>>(
        Shi, Slo, 2 * TT, (long long)TT * 2 * TT, vhi, vlo, DHV, (long long)TT * DHV,
        nullptr, outah, outal, DD, NH, 1, TT, 1.0f);

    // 8) final = outa . w_o^T (both bf16 hi/lo), fp32 out
    hgemm<false, false, false, 0><<<dim3(16, 16, 1), blk, SM128>>>(
        outah, outal, DD, 0, woh, wol, DD, 0,
        out, nullptr, nullptr, DD, 1, 0, DD, 1.0f);
}

// round 15
// speedup vs baseline: 1.9097x; 1.0526x over previous
#include <cuda_runtime.h>
#include <cuda_bf16.h>
#include <math.h>
#include <stdint.h>

#define TT 2048
#define DD 2048
#define NH 16
#define DHV 128
#define DRH 64
#define DCC 512
#define HDIM 192

typedef __nv_bfloat16 bf16;

// ---------------------------------------------------------------------------
// Scratch layout (bytes). bf16 tensors come as hi/lo pairs.
// ---------------------------------------------------------------------------
#define S_H     (2048ULL*2048*2)
#define S_WDKV  (512ULL*2048*2)
#define S_WDQ   (512ULL*2048*2)
#define S_WKR   (64ULL*2048*2)
#define S_WUK   (128ULL*16*512*2)
#define S_WUV   (128ULL*16*512*2)
#define S_WUQ   (128ULL*16*512*2)
#define S_WQR   (64ULL*16*512*2)
#define S_WO    (2048ULL*2048*2)
#define S_CKV   (2048ULL*512*2)
#define S_CQ    (2048ULL*512*2)
#define S_Q     (16ULL*2048*192*2)
#define S_K     (16ULL*2048*192*2)
#define S_V     (16ULL*2048*128*2)
#define S_OUTA  (2048ULL*2048*2)
#define S_KRP   (2048ULL*64*4)
#define S_QRP   (16ULL*2048*64*4)
#define S_LG    (16ULL*2048*2048*4)

#define O_HHI   0ULL
#define O_HLO   (O_HHI+S_H)
#define O_WDKVH (O_HLO+S_H)
#define O_WDKVL (O_WDKVH+S_WDKV)
#define O_WDQH  (O_WDKVL+S_WDKV)
#define O_WDQL  (O_WDQH+S_WDQ)
#define O_WKRH  (O_WDQL+S_WDQ)
#define O_WKRL  (O_WKRH+S_WKR)
#define O_WUKH  (O_WKRL+S_WKR)
#define O_WUKL  (O_WUKH+S_WUK)
#define O_WUVH  (O_WUKL+S_WUK)
#define O_WUVL  (O_WUVH+S_WUV)
#define O_WUQH  (O_WUVL+S_WUV)
#define O_WUQL  (O_WUQH+S_WUQ)
#define O_WQRH  (O_WUQL+S_WUQ)
#define O_WQRL  (O_WQRH+S_WQR)
#define O_WOH   (O_WQRL+S_WQR)
#define O_WOL   (O_WOH+S_WO)
#define O_CKVH  (O_WOL+S_WO)
#define O_CKVL  (O_CKVH+S_CKV)
#define O_CQH   (O_CKVL+S_CKV)
#define O_CQL   (O_CQH+S_CQ)
#define O_QHI   (O_CQL+S_CQ)
#define O_QLO   (O_QHI+S_Q)
#define O_KHI   (O_QLO+S_Q)
#define O_KLO   (O_KHI+S_K)
#define O_VHI   (O_KLO+S_K)
#define O_VLO   (O_VHI+S_V)
#define O_OUTAH (O_VLO+S_V)
#define O_OUTAL (O_OUTAH+S_OUTA)
#define O_KRP   (O_OUTAL+S_OUTA)
#define O_QRP   (O_KRP+S_KRP)
#define O_LG    (O_QRP+S_QRP)
#define SCRATCH_BYTES (O_LG+S_LG)

__device__ __align__(256) unsigned char g_scratch[SCRATCH_BYTES];

// ---------------------------------------------------------------------------
__device__ __forceinline__ uint32_t smem_u32(const void* p) {
    uint32_t a;
    asm("{ .reg .u64 t; cvta.to.shared.u64 t, %1; cvt.u32.u64 %0, t; }"
        : "=r"(a) : "l"(p));
    return a;
}
__device__ __forceinline__ void ldmx4(uint32_t* r, uint32_t addr) {
    asm volatile("ldmatrix.sync.aligned.m8n8.x4.shared.b16 {%0,%1,%2,%3}, [%4];"
                 : "=r"(r[0]), "=r"(r[1]), "=r"(r[2]), "=r"(r[3]) : "r"(addr));
}
__device__ __forceinline__ void ldmx4t(uint32_t* r, uint32_t addr) {
    asm volatile("ldmatrix.sync.aligned.m8n8.x4.trans.shared.b16 {%0,%1,%2,%3}, [%4];"
                 : "=r"(r[0]), "=r"(r[1]), "=r"(r[2]), "=r"(r[3]) : "r"(addr));
}
__device__ __forceinline__ void mma16816(float* c, const uint32_t* a,
                                         uint32_t b0, uint32_t b1) {
    asm volatile(
        "mma.sync.aligned.m16n8k16.row.col.f32.bf16.bf16.f32 "
        "{%0,%1,%2,%3}, {%4,%5,%6,%7}, {%8,%9}, {%0,%1,%2,%3};"
        : "+f"(c[0]), "+f"(c[1]), "+f"(c[2]), "+f"(c[3])
        : "r"(a[0]), "r"(a[1]), "r"(a[2]), "r"(a[3]), "r"(b0), "r"(b1));
}
__device__ __forceinline__ uint32_t bf2_u32(__nv_bfloat162 v) {
    return *reinterpret_cast<uint32_t*>(&v);
}
#define CP16(d, s) asm volatile("cp.async.cg.shared.global [%0], [%1], 16;" \
                                :: "r"(d), "l"(s))
#define CP_COMMIT() asm volatile("cp.async.commit_group;" ::: "memory")
#define CP_WAIT1()  asm volatile("cp.async.wait_group 1;" ::: "memory")
#define CP_WAIT0()  asm volatile("cp.async.wait_group 0;" ::: "memory")

__device__ __forceinline__ void wr_hl(bf16* hi, bf16* lo, size_t o, float v) {
    bf16 h = __float2bfloat16_rn(v);
    hi[o] = h;
    lo[o] = __float2bfloat16_rn(v - __bfloat162float(h));
}
__device__ __forceinline__ void wr_hl2(bf16* hi, bf16* lo, size_t o,
                                       float v0, float v1) {
    __nv_bfloat162 h = __floats2bfloat162_rn(v0, v1);
    float2 f = __bfloat1622float2(h);
    __nv_bfloat162 l = __floats2bfloat162_rn(v0 - f.x, v1 - f.y);
    *(uint32_t*)(hi + o) = bf2_u32(h);
    *(uint32_t*)(lo + o) = bf2_u32(l);
}

// ---------------------------------------------------------------------------
// Fused fp32 -> bf16 hi/lo split for all 9 tensors (one launch).
// ---------------------------------------------------------------------------
struct SplitArgs {
    const float* src[9];
    bf16* hi[9];
    bf16* lo[9];
    int n[9];
};

__global__ void split_all_kernel(SplitArgs a)
{
    int z = blockIdx.y;
    const float* __restrict__ src = a.src[z];
    bf16* __restrict__ hi = a.hi[z];
    bf16* __restrict__ lo = a.lo[z];
    int n = a.n[z];
    int stride = gridDim.x * blockDim.x * 4;
    for (int i = (blockIdx.x * blockDim.x + threadIdx.x) * 4; i < n; i += stride) {
        float4 v = *(const float4*)(src + i);
        __nv_bfloat162 h0 = __floats2bfloat162_rn(v.x, v.y);
        __nv_bfloat162 h1 = __floats2bfloat162_rn(v.z, v.w);
        float2 f0 = __bfloat1622float2(h0);
        float2 f1 = __bfloat1622float2(h1);
        __nv_bfloat162 l0 = __floats2bfloat162_rn(v.x - f0.x, v.y - f0.y);
        __nv_bfloat162 l1 = __floats2bfloat162_rn(v.z - f1.x, v.w - f1.y);
        *(uint2*)(hi + i) = make_uint2(bf2_u32(h0), bf2_u32(h1));
        *(uint2*)(lo + i) = make_uint2(bf2_u32(l0), bf2_u32(l1));
    }
}

// ---------------------------------------------------------------------------
// Segment descriptor for the fused projection GEMM.
// ---------------------------------------------------------------------------
struct Seg {
    const bf16* Bhi; const bf16* Blo;
    int ldb; long long strB;
    float* Cf; bf16* Chi; bf16* Clo;
    long long crs, strC;
    int epi;
};

// ---------------------------------------------------------------------------
// Fused multi-segment projection GEMM. M-tile=128, N-tile=64, BK=32,
// 3-stage cp.async pipeline, 2 CTAs/SM.
// ---------------------------------------------------------------------------
__global__ __launch_bounds__(256, 2)
void hgemm_fused(const bf16* __restrict__ Ahi, const bf16* __restrict__ Alo,
                 int lda, long long strA,
                 Seg s0, Seg s1, Seg s2, int t1, int t2, int K)
{
    constexpr int AB = 128 * 80, BB = 64 * 80;
    constexpr int oAL = AB, oBH = 2 * AB;
    constexpr int STAGE = 2 * AB + 2 * BB;   // 30720

    extern __shared__ char smarr[];
    const uint32_t smb = smem_u32(smarr);
    const int tid = threadIdx.x, wid = tid >> 5, lane = tid & 31;
    const int z = blockIdx.z;
    const int nt = blockIdx.x;
    const int m0 = blockIdx.y * 128;

    Seg sg = (nt < t1) ? s0 : (nt < t2) ? s1 : s2;
    const int base = (nt < t1) ? 0 : (nt < t2) ? t1 : t2;
    const int n0 = (nt - base) * 64;

    const bf16* Bh = sg.Bhi + (size_t)z * (size_t)sg.strB;
    const bf16* Bl = sg.Blo + (size_t)z * (size_t)sg.strB;
    Ahi += (size_t)z * (size_t)strA;  Alo += (size_t)z * (size_t)strA;

    const int niter = K / 32;

    auto issue = [&](int it) {
        const int kk0 = it * 32;
        const uint32_t sb = smb + (it % 3) * STAGE;
#pragma unroll
        for (int c = tid; c < 512; c += 256) {
            int row = c >> 2, kc = (c & 3) * 8;
            uint32_t d = sb + row * 80 + kc * 2;
            const bf16* s = Ahi + (size_t)(m0 + row) * lda + kk0 + kc;
            CP16(d, s);
            CP16(d + oAL, Alo + (s - Ahi));
        }
        {
            int c = tid;
            int row = c >> 2, kc = (c & 3) * 8;
            uint32_t d = sb + oBH + row * 80 + kc * 2;
            const bf16* s = Bh + (size_t)(n0 + row) * sg.ldb + kk0 + kc;
            CP16(d, s);
            CP16(d + BB, Bl + (s - Bh));
        }
    };

    float acc[2][4][4];
#pragma unroll
    for (int a = 0; a < 2; a++)
#pragma unroll
        for (int b = 0; b < 4; b++)
#pragma unroll
            for (int c = 0; c < 4; c++) acc[a][b][c] = 0.0f;

    const int wm  = (wid & 3) * 32;
    const int wnb = (wid >> 2) * 32;

    issue(0); CP_COMMIT();
    if (niter > 1) { issue(1); CP_COMMIT(); }

    for (int it = 0; it < niter; it++) {
        if (it + 1 < niter) CP_WAIT1(); else CP_WAIT0();
        __syncthreads();
        if (it + 2 < niter) { issue(it + 2); CP_COMMIT(); }

        const uint32_t sb = smb + (it % 3) * STAGE;
#pragma unroll
        for (int kk = 0; kk < 32; kk += 16) {
            uint32_t ah[2][4], al[2][4];
#pragma unroll
            for (int mt = 0; mt < 2; mt++) {
                int r = wm + mt * 16 + (lane & 15);
                uint32_t a = sb + r * 80 + kk * 2 + ((lane >> 4) << 4);
                ldmx4(ah[mt], a);
                ldmx4(al[mt], a + oAL);
            }
#pragma unroll
            for (int ng = 0; ng < 2; ng++) {
                uint32_t bh[4], bl[4];
                int r = wnb + ng * 16 + (lane & 15);
                uint32_t a = sb + oBH + r * 80 + kk * 2 + ((lane >> 4) << 4);
                ldmx4(bh, a);
                ldmx4(bl, a + BB);
#pragma unroll
                for (int hf = 0; hf < 2; hf++) {
#pragma unroll
                    for (int mt = 0; mt < 2; mt++) {
                        float* c = acc[mt][ng * 2 + hf];
                        mma16816(c, ah[mt], bh[hf], bh[hf + 2]);
                        mma16816(c, ah[mt], bl[hf], bl[hf + 2]);
                        mma16816(c, al[mt], bh[hf], bh[hf + 2]);
                    }
                }
            }
        }
        __syncthreads();
    }

    float* Cf = sg.Cf + (size_t)z * (size_t)(sg.epi == 0 ? sg.strC : 0);
    bf16* Chi = sg.Chi + (size_t)z * (size_t)(sg.epi == 1 ? sg.strC : 0);
    bf16* Clo = sg.Clo + (size_t)z * (size_t)(sg.epi == 1 ? sg.strC : 0);
#pragma unroll
    for (int mt = 0; mt < 2; mt++) {
#pragma unroll
        for (int nt8 = 0; nt8 < 4; nt8++) {
            int gm = m0 + wm + mt * 16 + (lane >> 2);
            int gn = n0 + wnb + nt8 * 8 + (lane & 3) * 2;
            float v0 = acc[mt][nt8][0];
            float v1 = acc[mt][nt8][1];
            float v2 = acc[mt][nt8][2];
            float v3 = acc[mt][nt8][3];
            if (sg.epi == 0) {
                *(float2*)&Cf[(size_t)gm * sg.crs + gn]       = make_float2(v0, v1);
                *(float2*)&Cf[(size_t)(gm + 8) * sg.crs + gn] = make_float2(v2, v3);
            } else {
                wr_hl2(Chi, Clo, (size_t)gm * sg.crs + gn, v0, v1);
                wr_hl2(Chi, Clo, (size_t)(gm + 8) * sg.crs + gn, v2, v3);
            }
        }
    }
}

// ---------------------------------------------------------------------------
// Generic NTILE=64 HMMA GEMM, 2 CTAs/SM, 3-stage cp.async pipeline.
// C[m,n] = alpha * sum_k A[m,k]*B[n,k].
// TRANS: A,B k-major in gmem; ldmatrix.trans (A pitch 272, B pitch 144).
// TRI: causal triangular grid at 128x64 tiles (tn <= 2*tm+1).
// CK: k starts at m0. EPI: 0 = fp32 out (alpha), 1 = bf16 hi/lo out.
// ---------------------------------------------------------------------------
template<bool TRANS, bool TRI, bool CK, int EPI>
__global__ __launch_bounds__(256, 2)
void hgemm64(const bf16* __restrict__ Ahi, const bf16* __restrict__ Alo,
             int lda, long long strA,
             const bf16* __restrict__ Bhi, const bf16* __restrict__ Blo,
             int ldb, long long strB,
             float* __restrict__ Cf, bf16* __restrict__ Chi, bf16* __restrict__ Clo,
             long long crs, long long ccs, long long strC,
             int K, float alpha)
{
    constexpr int AB  = TRANS ? 32 * 272 : 128 * 80;
    constexpr int BBs = TRANS ? 32 * 144 : 64 * 80;
    constexpr int oAL = AB, oBH = 2 * AB;
    constexpr int STAGE = 2 * AB + 2 * BBs;   // trans 26624 / non 30720

    extern __shared__ char smarr[];
    const uint32_t smb = smem_u32(smarr);
    const int tid = threadIdx.x, wid = tid >> 5, lane = tid & 31;
    const int z = blockIdx.z;
    Ahi += (size_t)z * (size_t)strA;  Alo += (size_t)z * (size_t)strA;
    Bhi += (size_t)z * (size_t)strB;  Blo += (size_t)z * (size_t)strB;
    if (EPI == 0) { Cf += (size_t)z * (size_t)strC; }
    else { Chi += (size_t)z * (size_t)strC; Clo += (size_t)z * (size_t)strC; }

    int m0, n0;
    if (TRI) {
        int x = blockIdx.x;
        int tm = (int)((sqrtf(4.0f * x + 1.0f) - 1.0f) * 0.5f);
        while ((tm + 1) * (tm + 2) <= x) tm++;
        while (tm * (tm + 1) > x) tm--;
        int tn = x - tm * (tm + 1);
        m0 = tm * 128; n0 = tn * 64;
    } else {
        m0 = blockIdx.y * 128;
        n0 = blockIdx.x * 64;
    }

    const int kbeg  = CK ? m0 : 0;
    const int niter = (K - kbeg) / 32;

    auto issue = [&](int it) {
        const int kk0 = kbeg + it * 32;
        const uint32_t sb = smb + (it % 3) * STAGE;
        if (!TRANS) {
#pragma unroll
            for (int c = tid; c < 512; c += 256) {
                int row = c >> 2, kc = (c & 3) * 8;
                uint32_t d = sb + row * 80 + kc * 2;
                const bf16* s = Ahi + (size_t)(m0 + row) * lda + kk0 + kc;
                CP16(d, s);
                CP16(d + oAL, Alo + (s - Ahi));
            }
            {
                int row = tid >> 2, kc = (tid & 3) * 8;
                uint32_t d = sb + oBH + row * 80 + kc * 2;
                const bf16* s = Bhi + (size_t)(n0 + row) * ldb + kk0 + kc;
                CP16(d, s);
                CP16(d + BBs, Blo + (s - Bhi));
            }
        } else {
#pragma unroll
            for (int c = tid; c < 512; c += 256) {
                int kr = c >> 4, mc = (c & 15) * 8;
                uint32_t d = sb + kr * 272 + mc * 2;
                const bf16* s = Ahi + (size_t)(kk0 + kr) * lda + m0 + mc;
                CP16(d, s);
                CP16(d + oAL, Alo + (s - Ahi));
            }
            {
                int kr = tid >> 3, nc = (tid & 7) * 8;
                uint32_t d = sb + oBH + kr * 144 + nc * 2;
                const bf16* s = Bhi + (size_t)(kk0 + kr) * ldb + n0 + nc;
                CP16(d, s);
                CP16(d + BBs, Blo + (s - Bhi));
            }
        }
    };

    float acc[2][4][4];
#pragma unroll
    for (int a = 0; a < 2; a++)
#pragma unroll
        for (int b = 0; b < 4; b++)
#pragma unroll
            for (int c = 0; c < 4; c++) acc[a][b][c] = 0.0f;

    const int wm  = (wid & 3) * 32;
    const int wnb = (wid >> 2) * 32;

    issue(0); CP_COMMIT();
    if (niter > 1) { issue(1); CP_COMMIT(); }

    for (int it = 0; it < niter; it++) {
        if (it + 1 < niter) CP_WAIT1(); else CP_WAIT0();
        __syncthreads();
        if (it + 2 < niter) { issue(it + 2); CP_COMMIT(); }

        const uint32_t sb = smb + (it % 3) * STAGE;
#pragma unroll
        for (int kk = 0; kk < 32; kk += 16) {
            uint32_t ah[2][4], al[2][4];
#pragma unroll
            for (int mt = 0; mt < 2; mt++) {
                if (!TRANS) {
                    int r = wm + mt * 16 + (lane & 15);
                    uint32_t a = sb + r * 80 + kk * 2 + ((lane >> 4) << 4);
                    ldmx4(ah[mt], a);
                    ldmx4(al[mt], a + oAL);
                } else {
                    int kr = kk + ((lane >> 4) << 3) + (lane & 7);
                    int mc = wm + mt * 16 + ((lane >> 3) & 1) * 8;
                    uint32_t a = sb + kr * 272 + mc * 2;
                    ldmx4t(ah[mt], a);
                    ldmx4t(al[mt], a + oAL);
                }
            }
#pragma unroll
            for (int ng = 0; ng < 2; ng++) {
                uint32_t bh[4], bl[4];
                if (!TRANS) {
                    int r = wnb + ng * 16 + (lane & 15);
                    uint32_t a = sb + oBH + r * 80 + kk * 2 + ((lane >> 4) << 4);
                    ldmx4(bh, a);
                    ldmx4(bl, a + BBs);
                } else {
                    int kr = kk + ((lane >> 4) << 3) + (lane & 7);
                    int nc = wnb + ng * 16 + ((lane >> 3) & 1) * 8;
                    uint32_t a = sb + oBH + kr * 144 + nc * 2;
                    ldmx4t(bh, a);
                    ldmx4t(bl, a + BBs);
                }
#pragma unroll
                for (int hf = 0; hf < 2; hf++) {
#pragma unroll
                    for (int mt = 0; mt < 2; mt++) {
                        float* c = acc[mt][ng * 2 + hf];
                        mma16816(c, ah[mt], bh[hf], bh[hf + 2]);
                        mma16816(c, ah[mt], bl[hf], bl[hf + 2]);
                        mma16816(c, al[mt], bh[hf], bh[hf + 2]);
                    }
                }
            }
        }
        __syncthreads();
    }

#pragma unroll
    for (int mt = 0; mt < 2; mt++) {
#pragma unroll
        for (int nt8 = 0; nt8 < 4; nt8++) {
            int gm = m0 + wm + mt * 16 + (lane >> 2);
            int gn = n0 + wnb + nt8 * 8 + (lane & 3) * 2;
            float v0 = acc[mt][nt8][0] * alpha;
            float v1 = acc[mt][nt8][1] * alpha;
            float v2 = acc[mt][nt8][2] * alpha;
            float v3 = acc[mt][nt8][3] * alpha;
            if (EPI == 0) {
                if (ccs == 1) {
                    *(float2*)&Cf[(size_t)gm * crs + gn]       = make_float2(v0, v1);
                    *(float2*)&Cf[(size_t)(gm + 8) * crs + gn] = make_float2(v2, v3);
                } else {
                    Cf[(size_t)gm * crs + (size_t)gn * ccs]             = v0;
                    Cf[(size_t)gm * crs + (size_t)(gn + 1) * ccs]       = v1;
                    Cf[(size_t)(gm + 8) * crs + (size_t)gn * ccs]       = v2;
                    Cf[(size_t)(gm + 8) * crs + (size_t)(gn + 1) * ccs] = v3;
                }
            } else {
                if (ccs == 1) {
                    wr_hl2(Chi, Clo, (size_t)gm * crs + gn, v0, v1);
                    wr_hl2(Chi, Clo, (size_t)(gm + 8) * crs + gn, v2, v3);
                } else {
                    wr_hl(Chi, Clo, (size_t)gm * crs + (size_t)gn * ccs, v0);
                    wr_hl(Chi, Clo, (size_t)gm * crs + (size_t)(gn + 1) * ccs, v1);
                    wr_hl(Chi, Clo, (size_t)(gm + 8) * crs + (size_t)gn * ccs, v2);
                    wr_hl(Chi, Clo, (size_t)(gm + 8) * crs + (size_t)(gn + 1) * ccs, v3);
                }
            }
        }
    }
}

// ---------------------------------------------------------------------------
// RoPE: q_r (fp32 temp) -> q hi/lo cols 128..191
// ---------------------------------------------------------------------------
__global__ void rope_q_split(const float* __restrict__ qrp, bf16* __restrict__ qhi,
                             bf16* __restrict__ qlo, const float* __restrict__ freqs)
{
    int idx = blockIdx.x * blockDim.x + threadIdx.x;
    if (idx >= NH * TT * 32) return;
    int i = idx & 31;
    int t = (idx >> 5) & (TT - 1);
    int n = idx >> 16;
    const float* src = qrp + ((size_t)n * TT + t) * DRH;
    float fr = freqs[t * 32 + i];
    float c = cosf(fr), s = sinf(fr);
    float re = src[i], im = src[i + 32];
    size_t base = ((size_t)n * TT + t) * HDIM + DHV;
    wr_hl(qhi, qlo, base + i,      re * c - im * s);
    wr_hl(qhi, qlo, base + i + 32, re * s + im * c);
}

__global__ void rope_k_split(const float* __restrict__ krp, bf16* __restrict__ khi,
                             bf16* __restrict__ klo, const float* __restrict__ freqs)
{
    int idx = blockIdx.x * blockDim.x + threadIdx.x;
    if (idx >= TT * 32) return;
    int i = idx & 31;
    int t = idx >> 5;
    float fr = freqs[t * 32 + i];
    float c = cosf(fr), s = sinf(fr);
    float re = krp[t * 64 + i];
    float im = krp[t * 64 + i + 32];
    float o1 = (re * c - im * s) * (1.0f / 16.0f);
    float o2 = (re * s + im * c) * (1.0f / 16.0f);
#pragma unroll
    for (int n = 0; n < NH; n++) {
        size_t base = ((size_t)n * TT + t) * HDIM + DHV;
        wr_hl(khi, klo, base + i, o1);
        wr_hl(khi, klo, base + i + 32, o2);
    }
}

// ---------------------------------------------------------------------------
// Causal softmax; writes S as bf16 hi/lo IN PLACE over the fp32 row:
// row's 8KB = [2048 hi bf16][2048 lo bf16].
// ---------------------------------------------------------------------------
__global__ __launch_bounds__(256)
void softmax_causal_split(float* __restrict__ L)
{
    int row = blockIdx.x;               // n*2048 + t
    int t = row & (TT - 1);
    int nvalid = t + 1;
    float* p = L + (size_t)row * TT;
    int tid = threadIdx.x;
    __shared__ float red[256];

    float v[8];
    float m = -3.4e38f;
#pragma unroll
    for (int k = 0; k < 8; k++) {
        int idx = tid + k * 256;
        v[k] = (idx < nvalid) ? p[idx] : -3.4e38f;
        m = fmaxf(m, v[k]);
    }
    red[tid] = m;
    __syncthreads();
    for (int s = 128; s > 0; s >>= 1) {
        if (tid < s) red[tid] = fmaxf(red[tid], red[tid + s]);
        __syncthreads();
    }
    m = red[0];
    __syncthreads();

    float sum = 0.0f;
#pragma unroll
    for (int k = 0; k < 8; k++) {
        v[k] = expf(v[k] - m);
        sum += v[k];
    }
    red[tid] = sum;
    __syncthreads();
    for (int s = 128; s > 0; s >>= 1) {
        if (tid < s) red[tid] += red[tid + s];
        __syncthreads();
    }
    float inv = 1.0f / red[0];
    __syncthreads();   // all reads of this row complete before aliased writes

    bf16* ph = (bf16*)p;
#pragma unroll
    for (int k = 0; k < 8; k++) {
        int idx = tid + k * 256;
        float val = (idx < nvalid) ? v[k] * inv : 0.0f;
        bf16 h = __float2bfloat16_rn(val);
        ph[idx]        = h;
        ph[2048 + idx] = __float2bfloat16_rn(val - __bfloat162float(h));
    }
}

// ---------------------------------------------------------------------------
extern "C" void kernel_launch(void* const* d_in, const int* in_sizes, int n_in,
                              void* d_out, int out_size)
{
    const float* h      = (const float*)d_in[0];
    const float* freqs  = (const float*)d_in[1];
    const float* w_dkv  = (const float*)d_in[3];
    const float* w_uk   = (const float*)d_in[4];
    const float* w_uv   = (const float*)d_in[5];
    const float* w_dq   = (const float*)d_in[6];
    const float* w_uq   = (const float*)d_in[7];
    const float* w_qr   = (const float*)d_in[8];
    const float* w_kr   = (const float*)d_in[9];
    const float* w_o    = (const float*)d_in[10];
    float* out = (float*)d_out;

    unsigned char* sc = nullptr;
    cudaGetSymbolAddress((void**)&sc, g_scratch);
    bf16* hhi   = (bf16*)(sc + O_HHI);   bf16* hlo   = (bf16*)(sc + O_HLO);
    bf16* wdkvh = (bf16*)(sc + O_WDKVH); bf16* wdkvl = (bf16*)(sc + O_WDKVL);
    bf16* wdqh  = (bf16*)(sc + O_WDQH);  bf16* wdql  = (bf16*)(sc + O_WDQL);
    bf16* wkrh  = (bf16*)(sc + O_WKRH);  bf16* wkrl  = (bf16*)(sc + O_WKRL);
    bf16* wukh  = (bf16*)(sc + O_WUKH);  bf16* wukl  = (bf16*)(sc + O_WUKL);
    bf16* wuvh  = (bf16*)(sc + O_WUVH);  bf16* wuvl  = (bf16*)(sc + O_WUVL);
    bf16* wuqh  = (bf16*)(sc + O_WUQH);  bf16* wuql  = (bf16*)(sc + O_WUQL);
    bf16* wqrh  = (bf16*)(sc + O_WQRH);  bf16* wqrl  = (bf16*)(sc + O_WQRL);
    bf16* woh   = (bf16*)(sc + O_WOH);   bf16* wol   = (bf16*)(sc + O_WOL);
    bf16* ckvh  = (bf16*)(sc + O_CKVH);  bf16* ckvl  = (bf16*)(sc + O_CKVL);
    bf16* cqh   = (bf16*)(sc + O_CQH);   bf16* cql   = (bf16*)(sc + O_CQL);
    bf16* qhi   = (bf16*)(sc + O_QHI);   bf16* qlo   = (bf16*)(sc + O_QLO);
    bf16* khi   = (bf16*)(sc + O_KHI);   bf16* klo   = (bf16*)(sc + O_KLO);
    bf16* vhi   = (bf16*)(sc + O_VHI);   bf16* vlo   = (bf16*)(sc + O_VLO);
    bf16* outah = (bf16*)(sc + O_OUTAH); bf16* outal = (bf16*)(sc + O_OUTAL);
    float* krp  = (float*)(sc + O_KRP);
    float* qrp  = (float*)(sc + O_QRP);
    float* lg   = (float*)(sc + O_LG);
    bf16* Shi   = (bf16*)(sc + O_LG);           // aliased: row = [2048 hi][2048 lo]
    bf16* Slo   = Shi + 2048;

    const int SMF  = 3 * (2 * 128 * 80 + 2 * 64 * 80);   //  92160 (fused / non-trans 64)
    const int SMTT = 3 * (2 * 32 * 272 + 2 * 32 * 144);  //  79872 (trans 64)
    cudaFuncSetAttribute(hgemm_fused,
                         cudaFuncAttributeMaxDynamicSharedMemorySize, SMF);
    cudaFuncSetAttribute(hgemm64<false, true, false, 0>,
                         cudaFuncAttributeMaxDynamicSharedMemorySize, SMF);
    cudaFuncSetAttribute(hgemm64<true, false, true, 1>,
                         cudaFuncAttributeMaxDynamicSharedMemorySize, SMTT);
    cudaFuncSetAttribute(hgemm64<false, false, false, 0>,
                         cudaFuncAttributeMaxDynamicSharedMemorySize, SMF);

    const float scale = 1.0f / sqrtf((float)HDIM);
    dim3 blk(256);

    // 0) split inputs + weights to bf16 hi/lo (single launch)
    SplitArgs sa;
    sa.src[0] = h;     sa.hi[0] = hhi;   sa.lo[0] = hlo;   sa.n[0] = 2048 * 2048;
    sa.src[1] = w_o;   sa.hi[1] = woh;   sa.lo[1] = wol;   sa.n[1] = 2048 * 2048;
    sa.src[2] = w_dkv; sa.hi[2] = wdkvh; sa.lo[2] = wdkvl; sa.n[2] = 512 * 2048;
    sa.src[3] = w_dq;  sa.hi[3] = wdqh;  sa.lo[3] = wdql;  sa.n[3] = 512 * 2048;
    sa.src[4] = w_uk;  sa.hi[4] = wukh;  sa.lo[4] = wukl;  sa.n[4] = 128 * 16 * 512;
    sa.src[5] = w_uv;  sa.hi[5] = wuvh;  sa.lo[5] = wuvl;  sa.n[5] = 128 * 16 * 512;
    sa.src[6] = w_uq;  sa.hi[6] = wuqh;  sa.lo[6] = wuql;  sa.n[6] = 128 * 16 * 512;
    sa.src[7] = w_qr;  sa.hi[7] = wqrh;  sa.lo[7] = wqrl;  sa.n[7] = 64 * 16 * 512;
    sa.src[8] = w_kr;  sa.hi[8] = wkrh;  sa.lo[8] = wkrl;  sa.n[8] = 64 * 2048;
    split_all_kernel<<<dim3(512, 9), 256>>>(sa);

    Seg zseg = {};

    // 1) fused down projection: h x [w_dkv | w_dq | w_kr]  (17 n-tiles)
    {
        Seg sdkv = { wdkvh, wdkvl, DD, 0, nullptr, ckvh, ckvl, DCC, 0, 1 };
        Seg sdq  = { wdqh,  wdql,  DD, 0, nullptr, cqh,  cql,  DCC, 0, 1 };
        Seg skr  = { wkrh,  wkrl,  DD, 0, krp, nullptr, nullptr, DRH, 0, 0 };
        hgemm_fused<<<dim3(17, 16, 1), blk, SMF>>>(
            hhi, hlo, DD, 0, sdkv, sdq, skr, 8, 16, DD);
    }

    // 2) fused q up-projection per head: c_q x [w_uq | w_qr]  (3 n-tiles)
    {
        Seg suq = { wuqh, wuql, NH * DCC, DCC,
                    nullptr, qhi, qlo, HDIM, (long long)TT * HDIM, 1 };
        Seg sqr = { wqrh, wqrl, NH * DCC, DCC,
                    qrp, nullptr, nullptr, DRH, (long long)TT * DRH, 0 };
        hgemm_fused<<<dim3(3, 16, NH), blk, SMF>>>(
            cqh, cql, DCC, 0, suq, sqr, zseg, 2, 3, DCC);
    }

    // 3) fused kv up-projection per head: c_kv x [w_uk | w_uv]  (4 n-tiles)
    //    (launch #4 — ncu control point)
    {
        Seg suk = { wukh, wukl, NH * DCC, DCC,
                    nullptr, khi, klo, HDIM, (long long)TT * HDIM, 1 };
        Seg suv = { wuvh, wuvl, NH * DCC, DCC,
                    nullptr, vhi, vlo, DHV, (long long)TT * DHV, 1 };
        hgemm_fused<<<dim3(4, 16, NH), blk, SMF>>>(
            ckvh, ckvl, DCC, 0, suk, suv, zseg, 2, 4, DCC);
    }

    // 4) RoPE -> q/k hi/lo cols 128..191
    rope_q_split<<<(NH * TT * 32 + 255) / 256, 256>>>(qrp, qhi, qlo, freqs);
    rope_k_split<<<(TT * 32 + 255) / 256, 256>>>(krp, khi, klo, freqs);

    // 5) logits = q k^T * scale; causal triangular grid at 128x64 (272/head)
    hgemm64<false, true, false, 0><<<dim3(272, 1, NH), blk, SMF>>>(
        qhi, qlo, HDIM, (long long)TT * HDIM, khi, klo, HDIM, (long long)TT * HDIM,
        lg, nullptr, nullptr, TT, 1, (long long)TT * TT, HDIM, scale);

    // 6) causal softmax; emits S as bf16 hi/lo in place
    softmax_causal_split<<<NH * TT, 256>>>(lg);

    // 7) out[l,e] = sum_t S[t,l] V[t,e]; trans staging, 2 n-tiles/head
    hgemm64<true, false, true, 1><<<dim3(2, 16, NH), blk, SMTT>>>(
        Shi, Slo, 2 * TT, (long long)TT * 2 * TT, vhi, vlo, DHV, (long long)TT * DHV,
        nullptr, outah, outal, DD, NH, 1, TT, 1.0f);

    // 8) final = outa . w_o^T (both bf16 hi/lo), fp32 out
    hgemm64<false, false, false, 0><<<dim3(32, 16, 1), blk, SMF>>>(
        outah, outal, DD, 0, woh, wol, DD, 0,
        out, nullptr, nullptr, DD, 1, 0, DD, 1.0f);
}

// round 17
// speedup vs baseline: 1.9545x; 1.0235x over previous
#include <cuda_runtime.h>
#include <cuda_bf16.h>
#include <math.h>
#include <stdint.h>

#define TT 2048
#define DD 2048
#define NH 16
#define DHV 128
#define DRH 64
#define DCC 512
#define HDIM 192

typedef __nv_bfloat16 bf16;

// ---------------------------------------------------------------------------
// Scratch layout (bytes). bf16 tensors come as hi/lo pairs.
// ---------------------------------------------------------------------------
#define S_H     (2048ULL*2048*2)
#define S_WDKV  (512ULL*2048*2)
#define S_WDQ   (512ULL*2048*2)
#define S_WKR   (64ULL*2048*2)
#define S_WUK   (128ULL*16*512*2)
#define S_WUV   (128ULL*16*512*2)
#define S_WUQ   (128ULL*16*512*2)
#define S_WQR   (64ULL*16*512*2)
#define S_WO    (2048ULL*2048*2)
#define S_CKV   (2048ULL*512*2)
#define S_CQ    (2048ULL*512*2)
#define S_Q     (16ULL*2048*192*2)
#define S_K     (16ULL*2048*192*2)
#define S_V     (16ULL*2048*128*2)
#define S_OUTA  (2048ULL*2048*2)
#define S_KRP   (2048ULL*64*4)
#define S_QRP   (16ULL*2048*64*4)
#define S_LG    (16ULL*2048*2048*4)

#define O_HHI   0ULL
#define O_HLO   (O_HHI+S_H)
#define O_WDKVH (O_HLO+S_H)
#define O_WDKVL (O_WDKVH+S_WDKV)
#define O_WDQH  (O_WDKVL+S_WDKV)
#define O_WDQL  (O_WDQH+S_WDQ)
#define O_WKRH  (O_WDQL+S_WDQ)
#define O_WKRL  (O_WKRH+S_WKR)
#define O_WUKH  (O_WKRL+S_WKR)
#define O_WUKL  (O_WUKH+S_WUK)
#define O_WUVH  (O_WUKL+S_WUK)
#define O_WUVL  (O_WUVH+S_WUV)
#define O_WUQH  (O_WUVL+S_WUV)
#define O_WUQL  (O_WUQH+S_WUQ)
#define O_WQRH  (O_WUQL+S_WUQ)
#define O_WQRL  (O_WQRH+S_WQR)
#define O_WOH   (O_WQRL+S_WQR)
#define O_WOL   (O_WOH+S_WO)
#define O_CKVH  (O_WOL+S_WO)
#define O_CKVL  (O_CKVH+S_CKV)
#define O_CQH   (O_CKVL+S_CKV)
#define O_CQL   (O_CQH+S_CQ)
#define O_QHI   (O_CQL+S_CQ)
#define O_QLO   (O_QHI+S_Q)
#define O_KHI   (O_QLO+S_Q)
#define O_KLO   (O_KHI+S_K)
#define O_VHI   (O_KLO+S_K)
#define O_VLO   (O_VHI+S_V)
#define O_OUTAH (O_VLO+S_V)
#define O_OUTAL (O_OUTAH+S_OUTA)
#define O_KRP   (O_OUTAL+S_OUTA)
#define O_QRP   (O_KRP+S_KRP)
#define O_LG    (O_QRP+S_QRP)
#define SCRATCH_BYTES (O_LG+S_LG)

__device__ __align__(256) unsigned char g_scratch[SCRATCH_BYTES];

// ---------------------------------------------------------------------------
__device__ __forceinline__ uint32_t smem_u32(const void* p) {
    uint32_t a;
    asm("{ .reg .u64 t; cvta.to.shared.u64 t, %1; cvt.u32.u64 %0, t; }"
        : "=r"(a) : "l"(p));
    return a;
}
__device__ __forceinline__ void ldmx4(uint32_t* r, uint32_t addr) {
    asm volatile("ldmatrix.sync.aligned.m8n8.x4.shared.b16 {%0,%1,%2,%3}, [%4];"
                 : "=r"(r[0]), "=r"(r[1]), "=r"(r[2]), "=r"(r[3]) : "r"(addr));
}
__device__ __forceinline__ void ldmx4t(uint32_t* r, uint32_t addr) {
    asm volatile("ldmatrix.sync.aligned.m8n8.x4.trans.shared.b16 {%0,%1,%2,%3}, [%4];"
                 : "=r"(r[0]), "=r"(r[1]), "=r"(r[2]), "=r"(r[3]) : "r"(addr));
}
__device__ __forceinline__ void mma16816(float* c, const uint32_t* a,
                                         uint32_t b0, uint32_t b1) {
    asm volatile(
        "mma.sync.aligned.m16n8k16.row.col.f32.bf16.bf16.f32 "
        "{%0,%1,%2,%3}, {%4,%5,%6,%7}, {%8,%9}, {%0,%1,%2,%3};"
        : "+f"(c[0]), "+f"(c[1]), "+f"(c[2]), "+f"(c[3])
        : "r"(a[0]), "r"(a[1]), "r"(a[2]), "r"(a[3]), "r"(b0), "r"(b1));
}
__device__ __forceinline__ uint32_t bf2_u32(__nv_bfloat162 v) {
    return *reinterpret_cast<uint32_t*>(&v);
}
#define CP16(d, s) asm volatile("cp.async.cg.shared.global [%0], [%1], 16;" \
                                :: "r"(d), "l"(s))
#define CP_COMMIT() asm volatile("cp.async.commit_group;" ::: "memory")
#define CP_WAIT1()  asm volatile("cp.async.wait_group 1;" ::: "memory")
#define CP_WAIT0()  asm volatile("cp.async.wait_group 0;" ::: "memory")

__device__ __forceinline__ void wr_hl(bf16* hi, bf16* lo, size_t o, float v) {
    bf16 h = __float2bfloat16_rn(v);
    hi[o] = h;
    lo[o] = __float2bfloat16_rn(v - __bfloat162float(h));
}
__device__ __forceinline__ void wr_hl2(bf16* hi, bf16* lo, size_t o,
                                       float v0, float v1) {
    __nv_bfloat162 h = __floats2bfloat162_rn(v0, v1);
    float2 f = __bfloat1622float2(h);
    __nv_bfloat162 l = __floats2bfloat162_rn(v0 - f.x, v1 - f.y);
    *(uint32_t*)(hi + o) = bf2_u32(h);
    *(uint32_t*)(lo + o) = bf2_u32(l);
}

// ---------------------------------------------------------------------------
// Fused fp32 -> bf16 hi/lo split for all 9 tensors (one launch).
// ---------------------------------------------------------------------------
struct SplitArgs {
    const float* src[9];
    bf16* hi[9];
    bf16* lo[9];
    int n[9];
};

__global__ void split_all_kernel(SplitArgs a)
{
    int z = blockIdx.y;
    const float* __restrict__ src = a.src[z];
    bf16* __restrict__ hi = a.hi[z];
    bf16* __restrict__ lo = a.lo[z];
    int n = a.n[z];
    int stride = gridDim.x * blockDim.x * 4;
    for (int i = (blockIdx.x * blockDim.x + threadIdx.x) * 4; i < n; i += stride) {
        float4 v = *(const float4*)(src + i);
        __nv_bfloat162 h0 = __floats2bfloat162_rn(v.x, v.y);
        __nv_bfloat162 h1 = __floats2bfloat162_rn(v.z, v.w);
        float2 f0 = __bfloat1622float2(h0);
        float2 f1 = __bfloat1622float2(h1);
        __nv_bfloat162 l0 = __floats2bfloat162_rn(v.x - f0.x, v.y - f0.y);
        __nv_bfloat162 l1 = __floats2bfloat162_rn(v.z - f1.x, v.w - f1.y);
        *(uint2*)(hi + i) = make_uint2(bf2_u32(h0), bf2_u32(h1));
        *(uint2*)(lo + i) = make_uint2(bf2_u32(l0), bf2_u32(l1));
    }
}

// ---------------------------------------------------------------------------
// Segment descriptor for the fused projection GEMM.
// ---------------------------------------------------------------------------
struct Seg {
    const bf16* Bhi; const bf16* Blo;
    int ldb; long long strB;
    float* Cf; bf16* Chi; bf16* Clo;
    long long crs, strC;
    int epi;
};

// ---------------------------------------------------------------------------
// Fused multi-segment projection GEMM. M-tile=128, N-tile=64, BK=32,
// 3-stage cp.async pipeline, 2 CTAs/SM.
// ---------------------------------------------------------------------------
__global__ __launch_bounds__(256, 2)
void hgemm_fused(const bf16* __restrict__ Ahi, const bf16* __restrict__ Alo,
                 int lda, long long strA,
                 Seg s0, Seg s1, Seg s2, int t1, int t2, int K)
{
    constexpr int AB = 128 * 80, BB = 64 * 80;
    constexpr int oAL = AB, oBH = 2 * AB;
    constexpr int STAGE = 2 * AB + 2 * BB;   // 30720

    extern __shared__ char smarr[];
    const uint32_t smb = smem_u32(smarr);
    const int tid = threadIdx.x, wid = tid >> 5, lane = tid & 31;
    const int z = blockIdx.z;
    const int nt = blockIdx.x;
    const int m0 = blockIdx.y * 128;

    Seg sg = (nt < t1) ? s0 : (nt < t2) ? s1 : s2;
    const int base = (nt < t1) ? 0 : (nt < t2) ? t1 : t2;
    const int n0 = (nt - base) * 64;

    const bf16* Bh = sg.Bhi + (size_t)z * (size_t)sg.strB;
    const bf16* Bl = sg.Blo + (size_t)z * (size_t)sg.strB;
    Ahi += (size_t)z * (size_t)strA;  Alo += (size_t)z * (size_t)strA;

    const int niter = K / 32;

    auto issue = [&](int it) {
        const int kk0 = it * 32;
        const uint32_t sb = smb + (it % 3) * STAGE;
#pragma unroll
        for (int c = tid; c < 512; c += 256) {
            int row = c >> 2, kc = (c & 3) * 8;
            uint32_t d = sb + row * 80 + kc * 2;
            const bf16* s = Ahi + (size_t)(m0 + row) * lda + kk0 + kc;
            CP16(d, s);
            CP16(d + oAL, Alo + (s - Ahi));
        }
        {
            int c = tid;
            int row = c >> 2, kc = (c & 3) * 8;
            uint32_t d = sb + oBH + row * 80 + kc * 2;
            const bf16* s = Bh + (size_t)(n0 + row) * sg.ldb + kk0 + kc;
            CP16(d, s);
            CP16(d + BB, Bl + (s - Bh));
        }
    };

    float acc[2][4][4];
#pragma unroll
    for (int a = 0; a < 2; a++)
#pragma unroll
        for (int b = 0; b < 4; b++)
#pragma unroll
            for (int c = 0; c < 4; c++) acc[a][b][c] = 0.0f;

    const int wm  = (wid & 3) * 32;
    const int wnb = (wid >> 2) * 32;

    issue(0); CP_COMMIT();
    if (niter > 1) { issue(1); CP_COMMIT(); }

    for (int it = 0; it < niter; it++) {
        if (it + 1 < niter) CP_WAIT1(); else CP_WAIT0();
        __syncthreads();
        if (it + 2 < niter) { issue(it + 2); CP_COMMIT(); }

        const uint32_t sb = smb + (it % 3) * STAGE;
#pragma unroll
        for (int kk = 0; kk < 32; kk += 16) {
            uint32_t ah[2][4], al[2][4];
#pragma unroll
            for (int mt = 0; mt < 2; mt++) {
                int r = wm + mt * 16 + (lane & 15);
                uint32_t a = sb + r * 80 + kk * 2 + ((lane >> 4) << 4);
                ldmx4(ah[mt], a);
                ldmx4(al[mt], a + oAL);
            }
#pragma unroll
            for (int ng = 0; ng < 2; ng++) {
                uint32_t bh[4], bl[4];
                int r = wnb + ng * 16 + (lane & 15);
                uint32_t a = sb + oBH + r * 80 + kk * 2 + ((lane >> 4) << 4);
                ldmx4(bh, a);
                ldmx4(bl, a + BB);
#pragma unroll
                for (int hf = 0; hf < 2; hf++) {
#pragma unroll
                    for (int mt = 0; mt < 2; mt++) {
                        float* c = acc[mt][ng * 2 + hf];
                        mma16816(c, ah[mt], bh[hf], bh[hf + 2]);
                        mma16816(c, ah[mt], bl[hf], bl[hf + 2]);
                        mma16816(c, al[mt], bh[hf], bh[hf + 2]);
                    }
                }
            }
        }
        __syncthreads();
    }

    float* Cf = sg.Cf + (size_t)z * (size_t)(sg.epi == 0 ? sg.strC : 0);
    bf16* Chi = sg.Chi + (size_t)z * (size_t)(sg.epi == 1 ? sg.strC : 0);
    bf16* Clo = sg.Clo + (size_t)z * (size_t)(sg.epi == 1 ? sg.strC : 0);
#pragma unroll
    for (int mt = 0; mt < 2; mt++) {
#pragma unroll
        for (int nt8 = 0; nt8 < 4; nt8++) {
            int gm = m0 + wm + mt * 16 + (lane >> 2);
            int gn = n0 + wnb + nt8 * 8 + (lane & 3) * 2;
            float v0 = acc[mt][nt8][0];
            float v1 = acc[mt][nt8][1];
            float v2 = acc[mt][nt8][2];
            float v3 = acc[mt][nt8][3];
            if (sg.epi == 0) {
                *(float2*)&Cf[(size_t)gm * sg.crs + gn]       = make_float2(v0, v1);
                *(float2*)&Cf[(size_t)(gm + 8) * sg.crs + gn] = make_float2(v2, v3);
            } else {
                wr_hl2(Chi, Clo, (size_t)gm * sg.crs + gn, v0, v1);
                wr_hl2(Chi, Clo, (size_t)(gm + 8) * sg.crs + gn, v2, v3);
            }
        }
    }
}

// ---------------------------------------------------------------------------
// Logits engine: M-tile=256, N-tile=64, warp tile 32x64 (8 warps all-m),
// BK=32, 2-stage cp.async double buffer, 2 CTAs/SM. Causal triangular grid
// at 256x64 tiles: C(tm)=2tm(tm+1), tn in [0, 4tm+4). fp32 epilogue * alpha.
// MMA:LDSM = 48:12 per warp-kk16 (vs 24:8 in the 32x32 warp tile).
// ---------------------------------------------------------------------------
__global__ __launch_bounds__(256, 2)
void hgemm256_tri(const bf16* __restrict__ Ahi, const bf16* __restrict__ Alo,
                  int lda, long long strA,
                  const bf16* __restrict__ Bhi, const bf16* __restrict__ Blo,
                  int ldb, long long strB,
                  float* __restrict__ Cf, long long crs, long long strC,
                  int K, float alpha)
{
    constexpr int AB = 256 * 80, BB = 64 * 80;
    constexpr int oAL = AB, oBH = 2 * AB;
    constexpr int STAGE = 2 * AB + 2 * BB;   // 51200

    extern __shared__ char smarr[];
    const uint32_t smb = smem_u32(smarr);
    const int tid = threadIdx.x, wid = tid >> 5, lane = tid & 31;
    const int z = blockIdx.z;
    Ahi += (size_t)z * (size_t)strA;  Alo += (size_t)z * (size_t)strA;
    Bhi += (size_t)z * (size_t)strB;  Blo += (size_t)z * (size_t)strB;
    Cf  += (size_t)z * (size_t)strC;

    // causal grid: cumulative C(tm) = 2*tm*(tm+1); 4*tm+4 n-tiles per tm
    int x = blockIdx.x;
    int tm = (int)(sqrtf(0.5f * x + 0.25f) - 0.5f);
    if (tm < 0) tm = 0;
    while (2 * (tm + 1) * (tm + 2) <= x) tm++;
    while (2 * tm * (tm + 1) > x) tm--;
    int tn = x - 2 * tm * (tm + 1);
    const int m0 = tm * 256, n0 = tn * 64;

    const int niter = K / 32;

    auto issue = [&](int it) {
        const int kk0 = it * 32;
        const uint32_t sb = smb + (it & 1) * STAGE;
#pragma unroll
        for (int c = tid; c < 1024; c += 256) {
            int row = c >> 2, kc = (c & 3) * 8;
            uint32_t d = sb + row * 80 + kc * 2;
            const bf16* s = Ahi + (size_t)(m0 + row) * lda + kk0 + kc;
            CP16(d, s);
            CP16(d + oAL, Alo + (s - Ahi));
        }
        {
            int row = tid >> 2, kc = (tid & 3) * 8;
            uint32_t d = sb + oBH + row * 80 + kc * 2;
            const bf16* s = Bhi + (size_t)(n0 + row) * ldb + kk0 + kc;
            CP16(d, s);
            CP16(d + BB, Blo + (s - Bhi));
        }
    };

    float acc[2][8][4];
#pragma unroll
    for (int a = 0; a < 2; a++)
#pragma unroll
        for (int b = 0; b < 8; b++)
#pragma unroll
            for (int c = 0; c < 4; c++) acc[a][b][c] = 0.0f;

    const int wm = wid * 32;   // 8 warps cover 256 m-rows; full 64 n per warp

    issue(0); CP_COMMIT();
    if (niter > 1) { issue(1); CP_COMMIT(); }

    for (int it = 0; it < niter; it++) {
        if (it + 1 < niter) CP_WAIT1(); else CP_WAIT0();
        __syncthreads();

        const uint32_t sb = smb + (it & 1) * STAGE;
#pragma unroll
        for (int kk = 0; kk < 32; kk += 16) {
            uint32_t ah[2][4], al[2][4];
#pragma unroll
            for (int mt = 0; mt < 2; mt++) {
                int r = wm + mt * 16 + (lane & 15);
                uint32_t a = sb + r * 80 + kk * 2 + ((lane >> 4) << 4);
                ldmx4(ah[mt], a);
                ldmx4(al[mt], a + oAL);
            }
#pragma unroll
            for (int ng = 0; ng < 4; ng++) {
                uint32_t bh[4], bl[4];
                int r = ng * 16 + (lane & 15);
                uint32_t a = sb + oBH + r * 80 + kk * 2 + ((lane >> 4) << 4);
                ldmx4(bh, a);
                ldmx4(bl, a + BB);
#pragma unroll
                for (int hf = 0; hf < 2; hf++) {
#pragma unroll
                    for (int mt = 0; mt < 2; mt++) {
                        float* c = acc[mt][ng * 2 + hf];
                        mma16816(c, ah[mt], bh[hf], bh[hf + 2]);
                        mma16816(c, ah[mt], bl[hf], bl[hf + 2]);
                        mma16816(c, al[mt], bh[hf], bh[hf + 2]);
                    }
                }
            }
        }
        __syncthreads();
        if (it + 2 < niter) { issue(it + 2); CP_COMMIT(); }
    }

#pragma unroll
    for (int mt = 0; mt < 2; mt++) {
#pragma unroll
        for (int nt8 = 0; nt8 < 8; nt8++) {
            int gm = m0 + wm + mt * 16 + (lane >> 2);
            int gn = n0 + nt8 * 8 + (lane & 3) * 2;
            float v0 = acc[mt][nt8][0] * alpha;
            float v1 = acc[mt][nt8][1] * alpha;
            float v2 = acc[mt][nt8][2] * alpha;
            float v3 = acc[mt][nt8][3] * alpha;
            *(float2*)&Cf[(size_t)gm * crs + gn]       = make_float2(v0, v1);
            *(float2*)&Cf[(size_t)(gm + 8) * crs + gn] = make_float2(v2, v3);
        }
    }
}

// ---------------------------------------------------------------------------
// Generic NTILE=64 HMMA GEMM, 2 CTAs/SM, 3-stage cp.async pipeline.
// TRANS: A,B k-major in gmem; ldmatrix.trans (A pitch 272, B pitch 144).
// CK: k starts at m0. EPI: 0 = fp32 out (alpha), 1 = bf16 hi/lo out.
// ---------------------------------------------------------------------------
template<bool TRANS, bool CK, int EPI>
__global__ __launch_bounds__(256, 2)
void hgemm64(const bf16* __restrict__ Ahi, const bf16* __restrict__ Alo,
             int lda, long long strA,
             const bf16* __restrict__ Bhi, const bf16* __restrict__ Blo,
             int ldb, long long strB,
             float* __restrict__ Cf, bf16* __restrict__ Chi, bf16* __restrict__ Clo,
             long long crs, long long ccs, long long strC,
             int K, float alpha)
{
    constexpr int AB  = TRANS ? 32 * 272 : 128 * 80;
    constexpr int BBs = TRANS ? 32 * 144 : 64 * 80;
    constexpr int oAL = AB, oBH = 2 * AB;
    constexpr int STAGE = 2 * AB + 2 * BBs;

    extern __shared__ char smarr[];
    const uint32_t smb = smem_u32(smarr);
    const int tid = threadIdx.x, wid = tid >> 5, lane = tid & 31;
    const int z = blockIdx.z;
    Ahi += (size_t)z * (size_t)strA;  Alo += (size_t)z * (size_t)strA;
    Bhi += (size_t)z * (size_t)strB;  Blo += (size_t)z * (size_t)strB;
    if (EPI == 0) { Cf += (size_t)z * (size_t)strC; }
    else { Chi += (size_t)z * (size_t)strC; Clo += (size_t)z * (size_t)strC; }

    const int m0 = blockIdx.y * 128;
    const int n0 = blockIdx.x * 64;

    const int kbeg  = CK ? m0 : 0;
    const int niter = (K - kbeg) / 32;

    auto issue = [&](int it) {
        const int kk0 = kbeg + it * 32;
        const uint32_t sb = smb + (it % 3) * STAGE;
        if (!TRANS) {
#pragma unroll
            for (int c = tid; c < 512; c += 256) {
                int row = c >> 2, kc = (c & 3) * 8;
                uint32_t d = sb + row * 80 + kc * 2;
                const bf16* s = Ahi + (size_t)(m0 + row) * lda + kk0 + kc;
                CP16(d, s);
                CP16(d + oAL, Alo + (s - Ahi));
            }
            {
                int row = tid >> 2, kc = (tid & 3) * 8;
                uint32_t d = sb + oBH + row * 80 + kc * 2;
                const bf16* s = Bhi + (size_t)(n0 + row) * ldb + kk0 + kc;
                CP16(d, s);
                CP16(d + BBs, Blo + (s - Bhi));
            }
        } else {
#pragma unroll
            for (int c = tid; c < 512; c += 256) {
                int kr = c >> 4, mc = (c & 15) * 8;
                uint32_t d = sb + kr * 272 + mc * 2;
                const bf16* s = Ahi + (size_t)(kk0 + kr) * lda + m0 + mc;
                CP16(d, s);
                CP16(d + oAL, Alo + (s - Ahi));
            }
            {
                int kr = tid >> 3, nc = (tid & 7) * 8;
                uint32_t d = sb + oBH + kr * 144 + nc * 2;
                const bf16* s = Bhi + (size_t)(kk0 + kr) * ldb + n0 + nc;
                CP16(d, s);
                CP16(d + BBs, Blo + (s - Bhi));
            }
        }
    };

    float acc[2][4][4];
#pragma unroll
    for (int a = 0; a < 2; a++)
#pragma unroll
        for (int b = 0; b < 4; b++)
#pragma unroll
            for (int c = 0; c < 4; c++) acc[a][b][c] = 0.0f;

    const int wm  = (wid & 3) * 32;
    const int wnb = (wid >> 2) * 32;

    issue(0); CP_COMMIT();
    if (niter > 1) { issue(1); CP_COMMIT(); }

    for (int it = 0; it < niter; it++) {
        if (it + 1 < niter) CP_WAIT1(); else CP_WAIT0();
        __syncthreads();
        if (it + 2 < niter) { issue(it + 2); CP_COMMIT(); }

        const uint32_t sb = smb + (it % 3) * STAGE;
#pragma unroll
        for (int kk = 0; kk < 32; kk += 16) {
            uint32_t ah[2][4], al[2][4];
#pragma unroll
            for (int mt = 0; mt < 2; mt++) {
                if (!TRANS) {
                    int r = wm + mt * 16 + (lane & 15);
                    uint32_t a = sb + r * 80 + kk * 2 + ((lane >> 4) << 4);
                    ldmx4(ah[mt], a);
                    ldmx4(al[mt], a + oAL);
                } else {
                    int kr = kk + ((lane >> 4) << 3) + (lane & 7);
                    int mc = wm + mt * 16 + ((lane >> 3) & 1) * 8;
                    uint32_t a = sb + kr * 272 + mc * 2;
                    ldmx4t(ah[mt], a);
                    ldmx4t(al[mt], a + oAL);
                }
            }
#pragma unroll
            for (int ng = 0; ng < 2; ng++) {
                uint32_t bh[4], bl[4];
                if (!TRANS) {
                    int r = wnb + ng * 16 + (lane & 15);
                    uint32_t a = sb + oBH + r * 80 + kk * 2 + ((lane >> 4) << 4);
                    ldmx4(bh, a);
                    ldmx4(bl, a + BBs);
                } else {
                    int kr = kk + ((lane >> 4) << 3) + (lane & 7);
                    int nc = wnb + ng * 16 + ((lane >> 3) & 1) * 8;
                    uint32_t a = sb + oBH + kr * 144 + nc * 2;
                    ldmx4t(bh, a);
                    ldmx4t(bl, a + BBs);
                }
#pragma unroll
                for (int hf = 0; hf < 2; hf++) {
#pragma unroll
                    for (int mt = 0; mt < 2; mt++) {
                        float* c = acc[mt][ng * 2 + hf];
                        mma16816(c, ah[mt], bh[hf], bh[hf + 2]);
                        mma16816(c, ah[mt], bl[hf], bl[hf + 2]);
                        mma16816(c, al[mt], bh[hf], bh[hf + 2]);
                    }
                }
            }
        }
        __syncthreads();
    }

#pragma unroll
    for (int mt = 0; mt < 2; mt++) {
#pragma unroll
        for (int nt8 = 0; nt8 < 4; nt8++) {
            int gm = m0 + wm + mt * 16 + (lane >> 2);
            int gn = n0 + wnb + nt8 * 8 + (lane & 3) * 2;
            float v0 = acc[mt][nt8][0] * alpha;
            float v1 = acc[mt][nt8][1] * alpha;
            float v2 = acc[mt][nt8][2] * alpha;
            float v3 = acc[mt][nt8][3] * alpha;
            if (EPI == 0) {
                if (ccs == 1) {
                    *(float2*)&Cf[(size_t)gm * crs + gn]       = make_float2(v0, v1);
                    *(float2*)&Cf[(size_t)(gm + 8) * crs + gn] = make_float2(v2, v3);
                } else {
                    Cf[(size_t)gm * crs + (size_t)gn * ccs]             = v0;
                    Cf[(size_t)gm * crs + (size_t)(gn + 1) * ccs]       = v1;
                    Cf[(size_t)(gm + 8) * crs + (size_t)gn * ccs]       = v2;
                    Cf[(size_t)(gm + 8) * crs + (size_t)(gn + 1) * ccs] = v3;
                }
            } else {
                if (ccs == 1) {
                    wr_hl2(Chi, Clo, (size_t)gm * crs + gn, v0, v1);
                    wr_hl2(Chi, Clo, (size_t)(gm + 8) * crs + gn, v2, v3);
                } else {
                    wr_hl(Chi, Clo, (size_t)gm * crs + (size_t)gn * ccs, v0);
                    wr_hl(Chi, Clo, (size_t)gm * crs + (size_t)(gn + 1) * ccs, v1);
                    wr_hl(Chi, Clo, (size_t)(gm + 8) * crs + (size_t)gn * ccs, v2);
                    wr_hl(Chi, Clo, (size_t)(gm + 8) * crs + (size_t)(gn + 1) * ccs, v3);
                }
            }
        }
    }
}

// ---------------------------------------------------------------------------
// RoPE: q_r (fp32 temp) -> q hi/lo cols 128..191
// ---------------------------------------------------------------------------
__global__ void rope_q_split(const float* __restrict__ qrp, bf16* __restrict__ qhi,
                             bf16* __restrict__ qlo, const float* __restrict__ freqs)
{
    int idx = blockIdx.x * blockDim.x + threadIdx.x;
    if (idx >= NH * TT * 32) return;
    int i = idx & 31;
    int t = (idx >> 5) & (TT - 1);
    int n = idx >> 16;
    const float* src = qrp + ((size_t)n * TT + t) * DRH;
    float fr = freqs[t * 32 + i];
    float c = cosf(fr), s = sinf(fr);
    float re = src[i], im = src[i + 32];
    size_t base = ((size_t)n * TT + t) * HDIM + DHV;
    wr_hl(qhi, qlo, base + i,      re * c - im * s);
    wr_hl(qhi, qlo, base + i + 32, re * s + im * c);
}

__global__ void rope_k_split(const float* __restrict__ krp, bf16* __restrict__ khi,
                             bf16* __restrict__ klo, const float* __restrict__ freqs)
{
    int idx = blockIdx.x * blockDim.x + threadIdx.x;
    if (idx >= TT * 32) return;
    int i = idx & 31;
    int t = idx >> 5;
    float fr = freqs[t * 32 + i];
    float c = cosf(fr), s = sinf(fr);
    float re = krp[t * 64 + i];
    float im = krp[t * 64 + i + 32];
    float o1 = (re * c - im * s) * (1.0f / 16.0f);
    float o2 = (re * s + im * c) * (1.0f / 16.0f);
#pragma unroll
    for (int n = 0; n < NH; n++) {
        size_t base = ((size_t)n * TT + t) * HDIM + DHV;
        wr_hl(khi, klo, base + i, o1);
        wr_hl(khi, klo, base + i + 32, o2);
    }
}

// ---------------------------------------------------------------------------
// Causal softmax; writes S as bf16 hi/lo IN PLACE over the fp32 row:
// row's 8KB = [2048 hi bf16][2048 lo bf16]. Zero-pads only up to
// round_up(t+1, 128): the out-GEMM (k-skip at 128-row granularity) never
// reads S[t][l] for l >= round_up(t+1,128).
// ---------------------------------------------------------------------------
__global__ __launch_bounds__(256)
void softmax_causal_split(float* __restrict__ L)
{
    int row = blockIdx.x;               // n*2048 + t
    int t = row & (TT - 1);
    int nvalid = t + 1;
    int wlim = (t + 128) & ~127;        // round_up(t+1, 128)
    float* p = L + (size_t)row * TT;
    int tid = threadIdx.x;
    __shared__ float red[256];

    float v[8];
    float m = -3.4e38f;
#pragma unroll
    for (int k = 0; k < 8; k++) {
        int idx = tid + k * 256;
        v[k] = (idx < nvalid) ? p[idx] : -3.4e38f;
        m = fmaxf(m, v[k]);
    }
    red[tid] = m;
    __syncthreads();
    for (int s = 128; s > 0; s >>= 1) {
        if (tid < s) red[tid] = fmaxf(red[tid], red[tid + s]);
        __syncthreads();
    }
    m = red[0];
    __syncthreads();

    float sum = 0.0f;
#pragma unroll
    for (int k = 0; k < 8; k++) {
        v[k] = expf(v[k] - m);
        sum += v[k];
    }
    red[tid] = sum;
    __syncthreads();
    for (int s = 128; s > 0; s >>= 1) {
        if (tid < s) red[tid] += red[tid + s];
        __syncthreads();
    }
    float inv = 1.0f / red[0];
    __syncthreads();   // all reads of this row complete before aliased writes

    bf16* ph = (bf16*)p;
#pragma unroll
    for (int k = 0; k < 8; k++) {
        int idx = tid + k * 256;
        if (idx < wlim) {
            float val = (idx < nvalid) ? v[k] * inv : 0.0f;
            bf16 h = __float2bfloat16_rn(val);
            ph[idx]        = h;
            ph[2048 + idx] = __float2bfloat16_rn(val - __bfloat162float(h));
        }
    }
}

// ---------------------------------------------------------------------------
extern "C" void kernel_launch(void* const* d_in, const int* in_sizes, int n_in,
                              void* d_out, int out_size)
{
    const float* h      = (const float*)d_in[0];
    const float* freqs  = (const float*)d_in[1];
    const float* w_dkv  = (const float*)d_in[3];
    const float* w_uk   = (const float*)d_in[4];
    const float* w_uv   = (const float*)d_in[5];
    const float* w_dq   = (const float*)d_in[6];
    const float* w_uq   = (const float*)d_in[7];
    const float* w_qr   = (const float*)d_in[8];
    const float* w_kr   = (const float*)d_in[9];
    const float* w_o    = (const float*)d_in[10];
    float* out = (float*)d_out;

    unsigned char* sc = nullptr;
    cudaGetSymbolAddress((void**)&sc, g_scratch);
    bf16* hhi   = (bf16*)(sc + O_HHI);   bf16* hlo   = (bf16*)(sc + O_HLO);
    bf16* wdkvh = (bf16*)(sc + O_WDKVH); bf16* wdkvl = (bf16*)(sc + O_WDKVL);
    bf16* wdqh  = (bf16*)(sc + O_WDQH);  bf16* wdql  = (bf16*)(sc + O_WDQL);
    bf16* wkrh  = (bf16*)(sc + O_WKRH);  bf16* wkrl  = (bf16*)(sc + O_WKRL);
    bf16* wukh  = (bf16*)(sc + O_WUKH);  bf16* wukl  = (bf16*)(sc + O_WUKL);
    bf16* wuvh  = (bf16*)(sc + O_WUVH);  bf16* wuvl  = (bf16*)(sc + O_WUVL);
    bf16* wuqh  = (bf16*)(sc + O_WUQH);  bf16* wuql  = (bf16*)(sc + O_WUQL);
    bf16* wqrh  = (bf16*)(sc + O_WQRH);  bf16* wqrl  = (bf16*)(sc + O_WQRL);
    bf16* woh   = (bf16*)(sc + O_WOH);   bf16* wol   = (bf16*)(sc + O_WOL);
    bf16* ckvh  = (bf16*)(sc + O_CKVH);  bf16* ckvl  = (bf16*)(sc + O_CKVL);
    bf16* cqh   = (bf16*)(sc + O_CQH);   bf16* cql   = (bf16*)(sc + O_CQL);
    bf16* qhi   = (bf16*)(sc + O_QHI);   bf16* qlo   = (bf16*)(sc + O_QLO);
    bf16* khi   = (bf16*)(sc + O_KHI);   bf16* klo   = (bf16*)(sc + O_KLO);
    bf16* vhi   = (bf16*)(sc + O_VHI);   bf16* vlo   = (bf16*)(sc + O_VLO);
    bf16* outah = (bf16*)(sc + O_OUTAH); bf16* outal = (bf16*)(sc + O_OUTAL);
    float* krp  = (float*)(sc + O_KRP);
    float* qrp  = (float*)(sc + O_QRP);
    float* lg   = (float*)(sc + O_LG);
    bf16* Shi   = (bf16*)(sc + O_LG);           // aliased: row = [2048 hi][2048 lo]
    bf16* Slo   = Shi + 2048;

    const int SMF  = 3 * (2 * 128 * 80 + 2 * 64 * 80);   //  92160 (fused / non-trans 64)
    const int SMTT = 3 * (2 * 32 * 272 + 2 * 32 * 144);  //  79872 (trans 64)
    const int SM256 = 2 * (2 * 256 * 80 + 2 * 64 * 80);  // 102400 (logits M256, 2-stage)
    cudaFuncSetAttribute(hgemm_fused,
                         cudaFuncAttributeMaxDynamicSharedMemorySize, SMF);
    cudaFuncSetAttribute(hgemm256_tri,
                         cudaFuncAttributeMaxDynamicSharedMemorySize, SM256);
    cudaFuncSetAttribute(hgemm64<true, true, 1>,
                         cudaFuncAttributeMaxDynamicSharedMemorySize, SMTT);
    cudaFuncSetAttribute(hgemm64<false, false, 0>,
                         cudaFuncAttributeMaxDynamicSharedMemorySize, SMF);

    const float scale = 1.0f / sqrtf((float)HDIM);
    dim3 blk(256);

    // 0) split inputs + weights to bf16 hi/lo (single launch)
    SplitArgs sa;
    sa.src[0] = h;     sa.hi[0] = hhi;   sa.lo[0] = hlo;   sa.n[0] = 2048 * 2048;
    sa.src[1] = w_o;   sa.hi[1] = woh;   sa.lo[1] = wol;   sa.n[1] = 2048 * 2048;
    sa.src[2] = w_dkv; sa.hi[2] = wdkvh; sa.lo[2] = wdkvl; sa.n[2] = 512 * 2048;
    sa.src[3] = w_dq;  sa.hi[3] = wdqh;  sa.lo[3] = wdql;  sa.n[3] = 512 * 2048;
    sa.src[4] = w_uk;  sa.hi[4] = wukh;  sa.lo[4] = wukl;  sa.n[4] = 128 * 16 * 512;
    sa.src[5] = w_uv;  sa.hi[5] = wuvh;  sa.lo[5] = wuvl;  sa.n[5] = 128 * 16 * 512;
    sa.src[6] = w_uq;  sa.hi[6] = wuqh;  sa.lo[6] = wuql;  sa.n[6] = 128 * 16 * 512;
    sa.src[7] = w_qr;  sa.hi[7] = wqrh;  sa.lo[7] = wqrl;  sa.n[7] = 64 * 16 * 512;
    sa.src[8] = w_kr;  sa.hi[8] = wkrh;  sa.lo[8] = wkrl;  sa.n[8] = 64 * 2048;
    split_all_kernel<<<dim3(512, 9), 256>>>(sa);

    Seg zseg = {};

    // 1) fused down projection: h x [w_dkv | w_dq | w_kr]  (17 n-tiles)
    {
        Seg sdkv = { wdkvh, wdkvl, DD, 0, nullptr, ckvh, ckvl, DCC, 0, 1 };
        Seg sdq  = { wdqh,  wdql,  DD, 0, nullptr, cqh,  cql,  DCC, 0, 1 };
        Seg skr  = { wkrh,  wkrl,  DD, 0, krp, nullptr, nullptr, DRH, 0, 0 };
        hgemm_fused<<<dim3(17, 16, 1), blk, SMF>>>(
            hhi, hlo, DD, 0, sdkv, sdq, skr, 8, 16, DD);
    }

    // 2) fused q up-projection per head: c_q x [w_uq | w_qr]  (3 n-tiles)
    {
        Seg suq = { wuqh, wuql, NH * DCC, DCC,
                    nullptr, qhi, qlo, HDIM, (long long)TT * HDIM, 1 };
        Seg sqr = { wqrh, wqrl, NH * DCC, DCC,
                    qrp, nullptr, nullptr, DRH, (long long)TT * DRH, 0 };
        hgemm_fused<<<dim3(3, 16, NH), blk, SMF>>>(
            cqh, cql, DCC, 0, suq, sqr, zseg, 2, 3, DCC);
    }

    // 3) fused kv up-projection per head: c_kv x [w_uk | w_uv]  (4 n-tiles)
    //    (launch #4 — ncu control point)
    {
        Seg suk = { wukh, wukl, NH * DCC, DCC,
                    nullptr, khi, klo, HDIM, (long long)TT * HDIM, 1 };
        Seg suv = { wuvh, wuvl, NH * DCC, DCC,
                    nullptr, vhi, vlo, DHV, (long long)TT * DHV, 1 };
        hgemm_fused<<<dim3(4, 16, NH), blk, SMF>>>(
            ckvh, ckvl, DCC, 0, suk, suv, zseg, 2, 4, DCC);
    }

    // 4) RoPE -> q/k hi/lo cols 128..191
    rope_q_split<<<(NH * TT * 32 + 255) / 256, 256>>>(qrp, qhi, qlo, freqs);
    rope_k_split<<<(TT * 32 + 255) / 256, 256>>>(krp, khi, klo, freqs);

    // 5) logits = q k^T * scale; M256 engine, causal grid (144 tiles/head)
    hgemm256_tri<<<dim3(144, 1, NH), blk, SM256>>>(
        qhi, qlo, HDIM, (long long)TT * HDIM, khi, klo, HDIM, (long long)TT * HDIM,
        lg, TT, (long long)TT * TT, HDIM, scale);

    // 6) causal softmax; emits S as bf16 hi/lo in place (bounded zero-pad)
    softmax_causal_split<<<NH * TT, 256>>>(lg);

    // 7) out[l,e] = sum_t S[t,l] V[t,e]; trans staging, 2 n-tiles/head
    hgemm64<true, true, 1><<<dim3(2, 16, NH), blk, SMTT>>>(
        Shi, Slo, 2 * TT, (long long)TT * 2 * TT, vhi, vlo, DHV, (long long)TT * DHV,
        nullptr, outah, outal, DD, NH, 1, TT, 1.0f);

    // 8) final = outa . w_o^T (both bf16 hi/lo), fp32 out
    hgemm64<false, false, 0><<<dim3(32, 16, 1), blk, SMF>>>(
        outah, outal, DD, 0, woh, wol, DD, 0,
        out, nullptr, nullptr, DD, 1, 0, DD, 1.0f);
}